// round 7
// baseline (speedup 1.0000x reference)
#include <cuda_runtime.h>
#include <cstdint>
#include <math.h>

#define S_LEN   1024
#define D_MODEL 768
#define DI_     1536
#define N_ST    16
#define K_CONV  4
#define DTRANK  48
#define XDP     256
#define VOCAB   32000
#define NL_     2
#define NCHUNK  8
#define CLEN    128
#define GROUPS  (DI_ * N_ST)

// ---------------- scratch ----------------
__device__ __align__(128) float g_x     [S_LEN * D_MODEL];
__device__ __align__(128) float g_xz    [S_LEN * 2 * DI_];
__device__ __align__(128) float g_xs    [S_LEN * DI_];
__device__ __align__(128) float g_xdbl  [S_LEN * XDP];
__device__ __align__(128) float g_dtl   [S_LEN * DI_];
__device__ __align__(128) float g_y     [S_LEN * DI_];
__device__ __align__(128) float g_tmp   [S_LEN * D_MODEL];
__device__ __align__(128) float g_wpad  [NL_][256 * DI_];
__device__ __align__(128) float g_dtwpad[NL_][DI_ * 64];
__device__ __align__(128) float g_wbig  [NL_][2 * DI_ * D_MODEL];
__device__ __align__(128) float g_wout  [NL_][D_MODEL * DI_];
__device__ __align__(128) float g_wh    [VOCAB * D_MODEL];
__device__ __align__(128) float g_P     [NCHUNK * GROUPS];
__device__ __align__(128) float g_H     [NCHUNK * GROUPS];
__device__ __align__(128) float g_C0    [NCHUNK * GROUPS];

// ---------------- helpers ----------------
__device__ __forceinline__ uint32_t smem_u32(const void* p) {
    uint32_t a;
    asm("{ .reg .u64 t; cvta.to.shared.u64 t, %1; cvt.u32.u64 %0, t; }" : "=r"(a) : "l"(p));
    return a;
}
__device__ __forceinline__ float rna_tf32(float v) {
    uint32_t t;
    asm("cvt.rna.tf32.f32 %0, %1;" : "=r"(t) : "f"(v));
    return __uint_as_float(t);
}
__device__ __forceinline__ float silu_f(float x) { return x / (1.0f + __expf(-x)); }

#define CP_ASYNC16(dst, src) \
    asm volatile("cp.async.cg.shared.global [%0], [%1], 16;" :: "r"(dst), "l"(src))
#define CP_COMMIT() asm volatile("cp.async.commit_group;" ::: "memory")
#define CP_WAIT(n)  asm volatile("cp.async.wait_group %0;" :: "n"(n) : "memory")
#define LDSM4(d0, d1, d2, d3, a) \
    asm volatile("ldmatrix.sync.aligned.m8n8.x4.shared.b16 {%0,%1,%2,%3}, [%4];" \
        : "=r"(d0), "=r"(d1), "=r"(d2), "=r"(d3) : "r"(a))

__device__ __forceinline__ void mma_tf32(float* c, const uint32_t* a, const uint32_t* b) {
    asm volatile(
        "mma.sync.aligned.m16n8k8.row.col.f32.tf32.tf32.f32 "
        "{%0,%1,%2,%3}, {%4,%5,%6,%7}, {%8,%9}, {%0,%1,%2,%3};"
        : "+f"(c[0]), "+f"(c[1]), "+f"(c[2]), "+f"(c[3])
        : "r"(a[0]), "r"(a[1]), "r"(a[2]), "r"(a[3]), "r"(b[0]), "r"(b[1]));
}

// ---------------- tf32 GEMM: C[M,N] = A[M,K]*B[N,K]^T -------------------------
// BM=64, BN=128, 8 warps (2x4 grid of 32x32 warp tiles), 3-stage cp.async.
// Occupancy-tuned: launch_bounds(256,3) -> <=85 regs, 3 CTAs/SM.
#define ASTG (64 * 32)
#define BSTG (128 * 32)
#define SMEM_GEMM (3 * (ASTG + BSTG) * 4)   // 73728

template<bool RC>
__global__ __launch_bounds__(256, 3)
void gemm_mma(const float* __restrict__ A, const float* __restrict__ B,
              float* __restrict__ C, int K, int lda, int ldb, int ldc)
{
    extern __shared__ float smem[];
    const int tid = threadIdx.x, lane = tid & 31, wid = tid >> 5;
    const int wm = wid >> 2, wn = wid & 3;        // 2x4 warp grid
    const int bm = blockIdx.x * 64, bn = blockIdx.y * 128;
    const int nc = K >> 5;
    const int lr = lane & 7, lg = lane >> 3;

    const uint32_t sb = smem_u32(smem);
    const float* Ab = A + (size_t)bm * lda;
    const float* Bb = B + (size_t)bn * ldb;

    auto loadA = [&](int chunk, int st) {
        uint32_t d0 = sb + st * (ASTG * 4);
        const float* s0 = Ab + chunk * 32;
#pragma unroll
        for (int it = 0; it < 2; it++) {
            int i = tid + it * 256;
            int r = i >> 3, q = i & 7;
            uint32_t off = ((uint32_t)r << 7) | (((uint32_t)q << 4) ^ (((uint32_t)(r & 7)) << 4));
            CP_ASYNC16(d0 + off, s0 + (size_t)r * lda + q * 4);
        }
    };
    auto loadB = [&](int chunk, int st) {
        uint32_t d0 = sb + (3 * ASTG + st * BSTG) * 4;
        const float* s0 = Bb + chunk * 32;
#pragma unroll
        for (int it = 0; it < 4; it++) {
            int i = tid + it * 256;
            int r = i >> 3, q = i & 7;
            uint32_t off = ((uint32_t)r << 7) | (((uint32_t)q << 4) ^ (((uint32_t)(r & 7)) << 4));
            CP_ASYNC16(d0 + off, s0 + (size_t)r * ldb + q * 4);
        }
    };

    const int a_row0 = wm * 32 + ((lg & 1) << 3) + lr;
    const int a_coff = (lg >> 1) << 2;
    const int b_row0 = wn * 32 + ((lg & 2) << 2) + lr;
    const int b_coff = (lg & 1) << 2;
    const uint32_t sw = (uint32_t)lr << 4;

    float acc[2][4][4];
#pragma unroll
    for (int i = 0; i < 2; i++)
#pragma unroll
        for (int j = 0; j < 4; j++)
#pragma unroll
            for (int v = 0; v < 4; v++) acc[i][j][v] = 0.0f;

    int npre = nc < 2 ? nc : 2;
    for (int c = 0; c < npre; c++) { loadA(c, c); loadB(c, c); CP_COMMIT(); }

    for (int i = 0; i < nc; i++) {
        if (i + 2 < nc) { CP_WAIT(1); } else { CP_WAIT(0); }
        __syncthreads();
        if (i + 2 < nc) {
            int s2 = (i + 2) % 3;
            loadA(i + 2, s2); loadB(i + 2, s2); CP_COMMIT();
        }
        uint32_t abase = sb + (i % 3) * (ASTG * 4);
        uint32_t bbase = sb + (3 * ASTG + (i % 3) * BSTG) * 4;
#pragma unroll
        for (int ks = 0; ks < 4; ks++) {
            const int k0 = ks * 8;
            uint32_t afr[2][4];
#pragma unroll
            for (int mf = 0; mf < 2; mf++) {
                uint32_t ad = abase + (uint32_t)(a_row0 + mf * 16) * 128 +
                              ((((uint32_t)(k0 + a_coff)) << 2) ^ sw);
                LDSM4(afr[mf][0], afr[mf][1], afr[mf][2], afr[mf][3], ad);
            }
            uint32_t bfr[4][2];
#pragma unroll
            for (int p = 0; p < 2; p++) {
                uint32_t bd = bbase + (uint32_t)(b_row0 + p * 16) * 128 +
                              ((((uint32_t)(k0 + b_coff)) << 2) ^ sw);
                LDSM4(bfr[2 * p][0], bfr[2 * p][1], bfr[2 * p + 1][0], bfr[2 * p + 1][1], bd);
            }
#pragma unroll
            for (int mf = 0; mf < 2; mf++)
#pragma unroll
                for (int nf = 0; nf < 4; nf++)
                    mma_tf32(acc[mf][nf], afr[mf], bfr[nf]);
        }
    }

#pragma unroll
    for (int mf = 0; mf < 2; mf++) {
        int row = bm + wm * 32 + mf * 16 + (lane >> 2);
#pragma unroll
        for (int nf = 0; nf < 4; nf++) {
            int col = bn + wn * 32 + nf * 8 + 2 * (lane & 3);
            float v0 = acc[mf][nf][0], v1 = acc[mf][nf][1];
            float v2 = acc[mf][nf][2], v3 = acc[mf][nf][3];
            if (RC) { v0 = rna_tf32(v0); v1 = rna_tf32(v1); v2 = rna_tf32(v2); v3 = rna_tf32(v3); }
            *(float2*)(C + (size_t)row * ldc + col)       = make_float2(v0, v1);
            *(float2*)(C + (size_t)(row + 8) * ldc + col) = make_float2(v2, v3);
        }
    }
}

// ---------------- elementwise / small kernels ----------------
__global__ void roundcopy4(float4* __restrict__ dst, const float4* __restrict__ src, int n4) {
    int i = blockIdx.x * blockDim.x + threadIdx.x;
    if (i < n4) {
        float4 v = src[i];
        v.x = rna_tf32(v.x); v.y = rna_tf32(v.y);
        v.z = rna_tf32(v.z); v.w = rna_tf32(v.w);
        dst[i] = v;
    }
}

__global__ void embed_kernel(const int* __restrict__ tokens,
                             const float* __restrict__ emb) {
    int i = blockIdx.x * blockDim.x + threadIdx.x;
    if (i < S_LEN * D_MODEL) {
        int l = i / D_MODEL, d = i - l * D_MODEL;
        g_x[i] = rna_tf32(emb[(size_t)tokens[l] * D_MODEL + d]);
    }
}

__global__ void padw_kernel(const float* __restrict__ xw, int L) {
    int i = blockIdx.x * 256 + threadIdx.x;
    if (i >= 256 * DI_) return;
    int row = i / DI_, col = i - row * DI_;
    g_wpad[L][i] = (row < 80) ? rna_tf32(xw[((size_t)L * 80 + row) * DI_ + col]) : 0.0f;
}

__global__ void paddt_kernel(const float* __restrict__ dw, int L) {
    int i = blockIdx.x * 256 + threadIdx.x;
    if (i >= DI_ * 64) return;
    int row = i >> 6, col = i & 63;
    g_dtwpad[L][i] = (col < DTRANK) ? rna_tf32(dw[((size_t)L * DI_ + row) * DTRANK + col]) : 0.0f;
}

__global__ void conv_silu_kernel(const float* __restrict__ conv_w,
                                 const float* __restrict__ conv_b, int layer) {
    int i = blockIdx.x * blockDim.x + threadIdx.x;
    if (i >= S_LEN * DI_) return;
    int t = i / DI_, c = i - t * DI_;
    const float* w = conv_w + ((size_t)layer * DI_ + c) * K_CONV;
    float acc = conv_b[layer * DI_ + c];
#pragma unroll
    for (int k = 0; k < K_CONV; k++) {
        int tt = t - (K_CONV - 1) + k;
        if (tt >= 0) acc += w[k] * g_xz[(size_t)tt * 2 * DI_ + c];
    }
    g_xs[i] = rna_tf32(silu_f(acc));
}

// ---------------- chunked selective scan ----------------
__global__ __launch_bounds__(256)
void scan_p1(const float* __restrict__ A_log, const float* __restrict__ dt_b, int layer) {
    int n  = threadIdx.x & 15;
    int cl = threadIdx.x >> 4;
    int c  = blockIdx.x * 16 + cl;
    int j  = blockIdx.y;
    float Acn  = -expf(A_log[((size_t)layer * DI_ + c) * N_ST + n]);
    float bias = dt_b[layer * DI_ + c];
    float h = 0.0f, p = 1.0f;
    int t0 = j * CLEN;
    for (int t = t0; t < t0 + CLEN; t++) {
        float a   = g_dtl[(size_t)t * DI_ + c] + bias;
        float dtv = (a > 20.0f) ? a : log1pf(__expf(a));
        float xv  = g_xs[(size_t)t * DI_ + c];
        float Bv  = g_xdbl[(size_t)t * XDP + DTRANK + n];
        float Cv  = g_xdbl[(size_t)t * XDP + DTRANK + N_ST + n];
        float dA  = __expf(dtv * Acn);
        h = dA * h + dtv * Bv * xv;
        p *= dA;
        float v = h * Cv;
#pragma unroll
        for (int o = 8; o > 0; o >>= 1)
            v += __shfl_down_sync(0xffffffffu, v, o, 16);
        if (n == 0) {
            g_y[(size_t)t * DI_ + c] = v;
            g_dtl[(size_t)t * DI_ + c] = dtv;
        }
    }
    int idx = c * N_ST + n;
    g_P[j * GROUPS + idx] = p;
    g_H[j * GROUPS + idx] = h;
}

__global__ void scan_p2() {
    int idx = blockIdx.x * blockDim.x + threadIdx.x;
    if (idx >= GROUPS) return;
    float carry = 0.0f;
#pragma unroll
    for (int j = 0; j < NCHUNK; j++) {
        g_C0[j * GROUPS + idx] = carry;
        carry = g_H[j * GROUPS + idx] + g_P[j * GROUPS + idx] * carry;
    }
}

__global__ __launch_bounds__(256)
void scan_p3(const float* __restrict__ A_log, const float* __restrict__ Dp, int layer) {
    int n  = threadIdx.x & 15;
    int cl = threadIdx.x >> 4;
    int c  = blockIdx.x * 16 + cl;
    int j  = blockIdx.y;
    float Acn = -expf(A_log[((size_t)layer * DI_ + c) * N_ST + n]);
    float Dpc = Dp[layer * DI_ + c];
    float carry = g_C0[j * GROUPS + c * N_ST + n];
    float p = 1.0f;
    int t0 = j * CLEN;
    if (j > 0) {
        for (int t = t0; t < t0 + CLEN; t++) {
            float dtv = g_dtl[(size_t)t * DI_ + c];
            float Cv  = g_xdbl[(size_t)t * XDP + DTRANK + N_ST + n];
            p *= __expf(dtv * Acn);
            float v = Cv * p * carry;
#pragma unroll
            for (int o = 8; o > 0; o >>= 1)
                v += __shfl_down_sync(0xffffffffu, v, o, 16);
            if (n == 0) {
                float xv = g_xs[(size_t)t * DI_ + c];
                float z  = g_xz[(size_t)t * 2 * DI_ + DI_ + c];
                g_y[(size_t)t * DI_ + c] =
                    rna_tf32((g_y[(size_t)t * DI_ + c] + v + xv * Dpc) * silu_f(z));
            }
        }
    } else {
        if (n == 0) {
            for (int t = t0; t < t0 + CLEN; t++) {
                float xv = g_xs[(size_t)t * DI_ + c];
                float z  = g_xz[(size_t)t * 2 * DI_ + DI_ + c];
                g_y[(size_t)t * DI_ + c] =
                    rna_tf32((g_y[(size_t)t * DI_ + c] + xv * Dpc) * silu_f(z));
            }
        }
    }
}

__global__ __launch_bounds__(256)
void ln_kernel(const float* __restrict__ gam, const float* __restrict__ bet, int layer) {
    int l = blockIdx.x;
    __shared__ float rsum[8], rsq[8];
    float sum = 0.0f, sq = 0.0f;
    for (int d = threadIdx.x; d < D_MODEL; d += 256) {
        float v = g_x[(size_t)l * D_MODEL + d] + g_tmp[(size_t)l * D_MODEL + d];
        sum += v; sq += v * v;
    }
#pragma unroll
    for (int o = 16; o > 0; o >>= 1) {
        sum += __shfl_down_sync(0xffffffffu, sum, o);
        sq  += __shfl_down_sync(0xffffffffu, sq, o);
    }
    int wid = threadIdx.x >> 5;
    if ((threadIdx.x & 31) == 0) { rsum[wid] = sum; rsq[wid] = sq; }
    __syncthreads();
    if (threadIdx.x == 0) {
        float s = 0.0f, q = 0.0f;
#pragma unroll
        for (int w = 0; w < 8; w++) { s += rsum[w]; q += rsq[w]; }
        rsum[0] = s; rsq[0] = q;
    }
    __syncthreads();
    float mu  = rsum[0] / (float)D_MODEL;
    float var = rsq[0] / (float)D_MODEL - mu * mu;
    float rinv = rsqrtf(var + 1e-5f);
    for (int d = threadIdx.x; d < D_MODEL; d += 256) {
        float v = g_x[(size_t)l * D_MODEL + d] + g_tmp[(size_t)l * D_MODEL + d];
        g_x[(size_t)l * D_MODEL + d] = rna_tf32(
            (v - mu) * rinv * gam[layer * D_MODEL + d] + bet[layer * D_MODEL + d]);
    }
}

// ---------------- launch ----------------
extern "C" void kernel_launch(void* const* d_in, const int* in_sizes, int n_in,
                              void* d_out, int out_size) {
    const int*   tokens  = (const int*)  d_in[0];
    const float* emb     = (const float*)d_in[1];
    const float* in_w    = (const float*)d_in[2];
    const float* conv_w  = (const float*)d_in[3];
    const float* conv_b  = (const float*)d_in[4];
    const float* xproj_w = (const float*)d_in[5];
    const float* dt_w    = (const float*)d_in[6];
    const float* dt_b    = (const float*)d_in[7];
    const float* A_log   = (const float*)d_in[8];
    const float* Dp      = (const float*)d_in[9];
    const float* out_w   = (const float*)d_in[10];
    const float* ln_g    = (const float*)d_in[11];
    const float* ln_b    = (const float*)d_in[12];
    const float* head_w  = (const float*)d_in[13];
    float* out = (float*)d_out;

    static float *px = nullptr, *pxz, *pxs, *pxdbl, *pdtl, *py, *ptmp, *pwh;
    static float *pwpad[NL_], *pdtw[NL_], *pwbig[NL_], *pwout[NL_];
    static cudaStream_t s1;
    static cudaEvent_t evFork, evWh, evJoin;
    static cudaEvent_t evIn[NL_], evPP[NL_], evOw[NL_];
    if (!px) {
        cudaGetSymbolAddress((void**)&pxz,   g_xz);
        cudaGetSymbolAddress((void**)&pxs,   g_xs);
        cudaGetSymbolAddress((void**)&pxdbl, g_xdbl);
        cudaGetSymbolAddress((void**)&pdtl,  g_dtl);
        cudaGetSymbolAddress((void**)&py,    g_y);
        cudaGetSymbolAddress((void**)&ptmp,  g_tmp);
        cudaGetSymbolAddress((void**)&pwh,   g_wh);
        float* base;
        cudaGetSymbolAddress((void**)&base, g_wpad);
        for (int L = 0; L < NL_; L++) pwpad[L] = base + (size_t)L * 256 * DI_;
        cudaGetSymbolAddress((void**)&base, g_dtwpad);
        for (int L = 0; L < NL_; L++) pdtw[L] = base + (size_t)L * DI_ * 64;
        cudaGetSymbolAddress((void**)&base, g_wbig);
        for (int L = 0; L < NL_; L++) pwbig[L] = base + (size_t)L * 2 * DI_ * D_MODEL;
        cudaGetSymbolAddress((void**)&base, g_wout);
        for (int L = 0; L < NL_; L++) pwout[L] = base + (size_t)L * D_MODEL * DI_;
        cudaFuncSetAttribute(gemm_mma<false>,
                             cudaFuncAttributeMaxDynamicSharedMemorySize, SMEM_GEMM);
        cudaFuncSetAttribute(gemm_mma<true>,
                             cudaFuncAttributeMaxDynamicSharedMemorySize, SMEM_GEMM);
        cudaStreamCreateWithFlags(&s1, cudaStreamNonBlocking);
        cudaEventCreateWithFlags(&evFork, cudaEventDisableTiming);
        cudaEventCreateWithFlags(&evWh,   cudaEventDisableTiming);
        cudaEventCreateWithFlags(&evJoin, cudaEventDisableTiming);
        for (int L = 0; L < NL_; L++) {
            cudaEventCreateWithFlags(&evIn[L], cudaEventDisableTiming);
            cudaEventCreateWithFlags(&evPP[L], cudaEventDisableTiming);
            cudaEventCreateWithFlags(&evOw[L], cudaEventDisableTiming);
        }
        cudaGetSymbolAddress((void**)&px, g_x);
    }

    cudaEventRecord(evFork, 0);
    cudaStreamWaitEvent(s1, evFork, 0);

    embed_kernel<<<(S_LEN * D_MODEL + 255) / 256, 256>>>(tokens, emb);

    roundcopy4<<<(2 * DI_ * D_MODEL / 4 + 255) / 256, 256, 0, s1>>>(
        (float4*)pwbig[0], (const float4*)in_w, 2 * DI_ * D_MODEL / 4);
    cudaEventRecord(evIn[0], s1);
    padw_kernel<<<(256 * DI_ + 255) / 256, 256, 0, s1>>>(xproj_w, 0);

    // in-proj L0 (profiled launch)
    cudaStreamWaitEvent(0, evIn[0], 0);
    gemm_mma<false><<<dim3(S_LEN / 64, 2 * DI_ / 128), 256, SMEM_GEMM>>>(
        px, pwbig[0], pxz, D_MODEL, D_MODEL, D_MODEL, 2 * DI_);

    paddt_kernel<<<(DI_ * 64 + 255) / 256, 256, 0, s1>>>(dt_w, 0);
    cudaEventRecord(evPP[0], s1);
    roundcopy4<<<(D_MODEL * DI_ / 4 + 255) / 256, 256, 0, s1>>>(
        (float4*)pwout[0], (const float4*)out_w, D_MODEL * DI_ / 4);
    cudaEventRecord(evOw[0], s1);
    roundcopy4<<<(2 * DI_ * D_MODEL / 4 + 255) / 256, 256, 0, s1>>>(
        (float4*)pwbig[1], (const float4*)(in_w + (size_t)2 * DI_ * D_MODEL),
        2 * DI_ * D_MODEL / 4);
    cudaEventRecord(evIn[1], s1);
    padw_kernel<<<(256 * DI_ + 255) / 256, 256, 0, s1>>>(xproj_w, 1);
    paddt_kernel<<<(DI_ * 64 + 255) / 256, 256, 0, s1>>>(dt_w, 1);
    cudaEventRecord(evPP[1], s1);
    roundcopy4<<<(D_MODEL * DI_ / 4 + 255) / 256, 256, 0, s1>>>(
        (float4*)pwout[1], (const float4*)(out_w + (size_t)D_MODEL * DI_),
        D_MODEL * DI_ / 4);
    cudaEventRecord(evOw[1], s1);
    roundcopy4<<<(VOCAB * D_MODEL / 4 + 255) / 256, 256, 0, s1>>>(
        (float4*)pwh, (const float4*)head_w, VOCAB * D_MODEL / 4);
    cudaEventRecord(evWh, s1);
    cudaEventRecord(evJoin, s1);

    for (int L = 0; L < NL_; L++) {
        if (L > 0) {
            cudaStreamWaitEvent(0, evIn[L], 0);
            gemm_mma<false><<<dim3(S_LEN / 64, 2 * DI_ / 128), 256, SMEM_GEMM>>>(
                px, pwbig[L], pxz, D_MODEL, D_MODEL, D_MODEL, 2 * DI_);
        }
        conv_silu_kernel<<<(S_LEN * DI_ + 255) / 256, 256>>>(conv_w, conv_b, L);

        cudaStreamWaitEvent(0, evPP[L], 0);
        gemm_mma<true><<<dim3(S_LEN / 64, XDP / 128), 256, SMEM_GEMM>>>(
            pxs, pwpad[L], pxdbl, DI_, DI_, DI_, XDP);
        gemm_mma<false><<<dim3(S_LEN / 64, DI_ / 128), 256, SMEM_GEMM>>>(
            pxdbl, pdtw[L], pdtl, 64, XDP, 64, DI_);

        scan_p1<<<dim3(DI_ / 16, NCHUNK), 256>>>(A_log, dt_b, L);
        scan_p2<<<(GROUPS + 255) / 256, 256>>>();
        scan_p3<<<dim3(DI_ / 16, NCHUNK), 256>>>(A_log, Dp, L);

        cudaStreamWaitEvent(0, evOw[L], 0);
        gemm_mma<false><<<dim3(S_LEN / 64, D_MODEL / 128), 256, SMEM_GEMM>>>(
            py, pwout[L], ptmp, DI_, DI_, DI_, D_MODEL);

        ln_kernel<<<S_LEN, 256>>>(ln_g, ln_b, L);
    }

    cudaStreamWaitEvent(0, evWh, 0);
    cudaStreamWaitEvent(0, evJoin, 0);
    gemm_mma<false><<<dim3(S_LEN / 64, VOCAB / 128), 256, SMEM_GEMM>>>(
        px, pwh, out, D_MODEL, D_MODEL, D_MODEL, VOCAB);
}

// round 8
// speedup vs baseline: 1.2665x; 1.2665x over previous
#include <cuda_runtime.h>
#include <cuda_fp16.h>
#include <cstdint>
#include <math.h>

#define S_LEN   1024
#define D_MODEL 768
#define DI_     1536
#define N_ST    16
#define K_CONV  4
#define DTRANK  48
#define XDP     256
#define VOCAB   32000
#define NL_     2
#define NCHUNK  8
#define CLEN    128
#define GROUPS  (DI_ * N_ST)

// ---------------- scratch ----------------
__device__ __align__(128) float  g_x    [S_LEN * D_MODEL];   // residual (fp32)
__device__ __align__(128) __half g_xh   [S_LEN * D_MODEL];   // half copy for GEMM A
__device__ __align__(128) float  g_xz   [S_LEN * 2 * DI_];
__device__ __align__(128) __half g_xsh  [S_LEN * DI_];       // conv out (half)
__device__ __align__(128) __half g_xdblh[S_LEN * XDP];       // xproj out (half)
__device__ __align__(128) float  g_dtl  [S_LEN * DI_];
__device__ __align__(128) float  g_y    [S_LEN * DI_];
__device__ __align__(128) __half g_yh   [S_LEN * DI_];       // gated out (half)
__device__ __align__(128) float  g_tmp  [S_LEN * D_MODEL];
__device__ __align__(128) __half g_wpad  [NL_][256 * DI_];
__device__ __align__(128) __half g_dtwpad[NL_][DI_ * 64];
__device__ __align__(128) __half g_wbig  [NL_][2 * DI_ * D_MODEL];
__device__ __align__(128) __half g_wout  [NL_][D_MODEL * DI_];
__device__ __align__(128) __half g_wh    [VOCAB * D_MODEL];
__device__ __align__(128) float  g_P  [NCHUNK * GROUPS];
__device__ __align__(128) float  g_H  [NCHUNK * GROUPS];
__device__ __align__(128) float  g_C0 [NCHUNK * GROUPS];

// ---------------- helpers ----------------
__device__ __forceinline__ uint32_t smem_u32(const void* p) {
    uint32_t a;
    asm("{ .reg .u64 t; cvta.to.shared.u64 t, %1; cvt.u32.u64 %0, t; }" : "=r"(a) : "l"(p));
    return a;
}
__device__ __forceinline__ float silu_f(float x) { return x / (1.0f + __expf(-x)); }

#define CP_ASYNC16(dst, src) \
    asm volatile("cp.async.cg.shared.global [%0], [%1], 16;" :: "r"(dst), "l"(src))
#define CP_COMMIT() asm volatile("cp.async.commit_group;" ::: "memory")
#define CP_WAIT(n)  asm volatile("cp.async.wait_group %0;" :: "n"(n) : "memory")
#define LDSM4(d0, d1, d2, d3, a) \
    asm volatile("ldmatrix.sync.aligned.m8n8.x4.shared.b16 {%0,%1,%2,%3}, [%4];" \
        : "=r"(d0), "=r"(d1), "=r"(d2), "=r"(d3) : "r"(a))

__device__ __forceinline__ void mma_f16(float* c, const uint32_t* a, const uint32_t* b) {
    asm volatile(
        "mma.sync.aligned.m16n8k16.row.col.f32.f16.f16.f32 "
        "{%0,%1,%2,%3}, {%4,%5,%6,%7}, {%8,%9}, {%0,%1,%2,%3};"
        : "+f"(c[0]), "+f"(c[1]), "+f"(c[2]), "+f"(c[3])
        : "r"(a[0]), "r"(a[1]), "r"(a[2]), "r"(a[3]), "r"(b[0]), "r"(b[1]));
}

// ---------------- fp16 GEMM: C[M,N] = A[M,K]*B[N,K]^T -------------------------
// BM=128, BN=128, KC=64, 8 warps (2x4, warp tile 64x32), 3-stage cp.async.
// A,B half (K-contiguous). K % 64 == 0. 2 CTAs/SM.
#define STG_B 16384                      // bytes per matrix per stage (128 rows x 128B)
#define SMEM_GEMM (3 * 2 * STG_B)        // 98304

template<bool OH>
__global__ __launch_bounds__(256, 2)
void gemm_h(const __half* __restrict__ A, const __half* __restrict__ B,
            void* __restrict__ Cv, int K, int lda, int ldb, int ldc)
{
    extern __shared__ char smem[];
    const int tid = threadIdx.x, lane = tid & 31, wid = tid >> 5;
    const int wm = wid >> 2, wn = wid & 3;
    const int bm = blockIdx.x * 128, bn = blockIdx.y * 128;
    const int nc = K >> 6;
    const int lr = lane & 7, lg = lane >> 3;

    const uint32_t sb = smem_u32(smem);
    const __half* Ab = A + (size_t)bm * lda;
    const __half* Bb = B + (size_t)bn * ldb;

    auto loadA = [&](int chunk, int st) {
        uint32_t d0 = sb + st * (2 * STG_B);
        const __half* s0 = Ab + chunk * 64;
#pragma unroll
        for (int it = 0; it < 4; it++) {
            int i = tid + it * 256;
            int r = i >> 3, q = i & 7;
            uint32_t off = ((uint32_t)r << 7) | (((uint32_t)q << 4) ^ (((uint32_t)(r & 7)) << 4));
            CP_ASYNC16(d0 + off, s0 + (size_t)r * lda + q * 8);
        }
    };
    auto loadB = [&](int chunk, int st) {
        uint32_t d0 = sb + st * (2 * STG_B) + STG_B;
        const __half* s0 = Bb + chunk * 64;
#pragma unroll
        for (int it = 0; it < 4; it++) {
            int i = tid + it * 256;
            int r = i >> 3, q = i & 7;
            uint32_t off = ((uint32_t)r << 7) | (((uint32_t)q << 4) ^ (((uint32_t)(r & 7)) << 4));
            CP_ASYNC16(d0 + off, s0 + (size_t)r * ldb + q * 8);
        }
    };

    // ldmatrix address components (b16, 128B rows)
    const int a_row0 = wm * 64 + ((lg & 1) << 3) + lr;   // lanes 8-15 -> +8 rows
    const int a_coff = (lg >> 1) << 4;                   // lanes 16+ -> +16B (k8-15)
    const int b_row0 = wn * 32 + ((lg & 2) << 2) + lr;   // lanes 16+ -> +8 n-rows
    const int b_coff = (lg & 1) << 4;                    // odd lg -> +16B
    const uint32_t sw = (uint32_t)lr << 4;

    float acc[4][4][4];
#pragma unroll
    for (int i = 0; i < 4; i++)
#pragma unroll
        for (int j = 0; j < 4; j++)
#pragma unroll
            for (int v = 0; v < 4; v++) acc[i][j][v] = 0.0f;

    int npre = nc < 2 ? nc : 2;
    for (int c = 0; c < npre; c++) { loadA(c, c); loadB(c, c); CP_COMMIT(); }

    for (int i = 0; i < nc; i++) {
        if (i + 2 < nc) { CP_WAIT(1); } else { CP_WAIT(0); }
        __syncthreads();
        if (i + 2 < nc) {
            int s2 = (i + 2) % 3;
            loadA(i + 2, s2); loadB(i + 2, s2); CP_COMMIT();
        }
        uint32_t abase = sb + (i % 3) * (2 * STG_B);
        uint32_t bbase = abase + STG_B;
#pragma unroll
        for (int ks = 0; ks < 4; ks++) {                 // 4 x k16
            const uint32_t kb = (uint32_t)ks * 32;
            uint32_t afr[4][4];
#pragma unroll
            for (int mf = 0; mf < 4; mf++) {
                uint32_t ad = abase + (uint32_t)(a_row0 + mf * 16) * 128 +
                              ((kb + a_coff) ^ sw);
                LDSM4(afr[mf][0], afr[mf][1], afr[mf][2], afr[mf][3], ad);
            }
            uint32_t bfr[4][2];
#pragma unroll
            for (int p = 0; p < 2; p++) {
                uint32_t bd = bbase + (uint32_t)(b_row0 + p * 16) * 128 +
                              ((kb + b_coff) ^ sw);
                LDSM4(bfr[2 * p][0], bfr[2 * p][1], bfr[2 * p + 1][0], bfr[2 * p + 1][1], bd);
            }
#pragma unroll
            for (int mf = 0; mf < 4; mf++)
#pragma unroll
                for (int nf = 0; nf < 4; nf++)
                    mma_f16(acc[mf][nf], afr[mf], bfr[nf]);
        }
    }

#pragma unroll
    for (int mf = 0; mf < 4; mf++) {
        int row = bm + wm * 64 + mf * 16 + (lane >> 2);
#pragma unroll
        for (int nf = 0; nf < 4; nf++) {
            int col = bn + wn * 32 + nf * 8 + 2 * (lane & 3);
            if (OH) {
                __half* C = (__half*)Cv;
                *(__half2*)(C + (size_t)row * ldc + col) =
                    __floats2half2_rn(acc[mf][nf][0], acc[mf][nf][1]);
                *(__half2*)(C + (size_t)(row + 8) * ldc + col) =
                    __floats2half2_rn(acc[mf][nf][2], acc[mf][nf][3]);
            } else {
                float* C = (float*)Cv;
                *(float2*)(C + (size_t)row * ldc + col) =
                    make_float2(acc[mf][nf][0], acc[mf][nf][1]);
                *(float2*)(C + (size_t)(row + 8) * ldc + col) =
                    make_float2(acc[mf][nf][2], acc[mf][nf][3]);
            }
        }
    }
}

// ---------------- elementwise / small kernels ----------------
__global__ void roundcopy_h(__half2* __restrict__ dst, const float4* __restrict__ src, int n4) {
    int i = blockIdx.x * blockDim.x + threadIdx.x;
    if (i < n4) {
        float4 v = src[i];
        dst[2 * i]     = __floats2half2_rn(v.x, v.y);
        dst[2 * i + 1] = __floats2half2_rn(v.z, v.w);
    }
}

__global__ void embed_kernel(const int* __restrict__ tokens,
                             const float* __restrict__ emb) {
    int i = blockIdx.x * blockDim.x + threadIdx.x;
    if (i < S_LEN * D_MODEL) {
        int l = i / D_MODEL, d = i - l * D_MODEL;
        float e = emb[(size_t)tokens[l] * D_MODEL + d];
        g_x[i]  = e;
        g_xh[i] = __float2half_rn(e);
    }
}

__global__ void padw_kernel(const float* __restrict__ xw, int L) {
    int i = blockIdx.x * 256 + threadIdx.x;
    if (i >= 256 * DI_) return;
    int row = i / DI_, col = i - row * DI_;
    g_wpad[L][i] = (row < 80) ? __float2half_rn(xw[((size_t)L * 80 + row) * DI_ + col])
                              : __half(0.0f);
}

__global__ void paddt_kernel(const float* __restrict__ dw, int L) {
    int i = blockIdx.x * 256 + threadIdx.x;
    if (i >= DI_ * 64) return;
    int row = i >> 6, col = i & 63;
    g_dtwpad[L][i] = (col < DTRANK) ? __float2half_rn(dw[((size_t)L * DI_ + row) * DTRANK + col])
                                    : __half(0.0f);
}

__global__ void conv_silu_kernel(const float* __restrict__ conv_w,
                                 const float* __restrict__ conv_b, int layer) {
    int i = blockIdx.x * blockDim.x + threadIdx.x;
    if (i >= S_LEN * DI_) return;
    int t = i / DI_, c = i - t * DI_;
    const float* w = conv_w + ((size_t)layer * DI_ + c) * K_CONV;
    float acc = conv_b[layer * DI_ + c];
#pragma unroll
    for (int k = 0; k < K_CONV; k++) {
        int tt = t - (K_CONV - 1) + k;
        if (tt >= 0) acc += w[k] * g_xz[(size_t)tt * 2 * DI_ + c];
    }
    g_xsh[i] = __float2half_rn(silu_f(acc));
}

// ---------------- chunked selective scan ----------------
__global__ __launch_bounds__(256)
void scan_p1(const float* __restrict__ A_log, const float* __restrict__ dt_b, int layer) {
    int n  = threadIdx.x & 15;
    int cl = threadIdx.x >> 4;
    int c  = blockIdx.x * 16 + cl;
    int j  = blockIdx.y;
    float Acn  = -expf(A_log[((size_t)layer * DI_ + c) * N_ST + n]);
    float bias = dt_b[layer * DI_ + c];
    float h = 0.0f, p = 1.0f;
    int t0 = j * CLEN;
    for (int t = t0; t < t0 + CLEN; t++) {
        float a   = g_dtl[(size_t)t * DI_ + c] + bias;
        float dtv = (a > 20.0f) ? a : log1pf(__expf(a));
        float xv  = __half2float(g_xsh[(size_t)t * DI_ + c]);
        float Bv  = __half2float(g_xdblh[(size_t)t * XDP + DTRANK + n]);
        float Cv  = __half2float(g_xdblh[(size_t)t * XDP + DTRANK + N_ST + n]);
        float dA  = __expf(dtv * Acn);
        h = dA * h + dtv * Bv * xv;
        p *= dA;
        float v = h * Cv;
#pragma unroll
        for (int o = 8; o > 0; o >>= 1)
            v += __shfl_down_sync(0xffffffffu, v, o, 16);
        if (n == 0) {
            g_y[(size_t)t * DI_ + c] = v;
            g_dtl[(size_t)t * DI_ + c] = dtv;
        }
    }
    int idx = c * N_ST + n;
    g_P[j * GROUPS + idx] = p;
    g_H[j * GROUPS + idx] = h;
}

__global__ void scan_p2() {
    int idx = blockIdx.x * blockDim.x + threadIdx.x;
    if (idx >= GROUPS) return;
    float carry = 0.0f;
#pragma unroll
    for (int j = 0; j < NCHUNK; j++) {
        g_C0[j * GROUPS + idx] = carry;
        carry = g_H[j * GROUPS + idx] + g_P[j * GROUPS + idx] * carry;
    }
}

__global__ __launch_bounds__(256)
void scan_p3(const float* __restrict__ A_log, const float* __restrict__ Dp, int layer) {
    int n  = threadIdx.x & 15;
    int cl = threadIdx.x >> 4;
    int c  = blockIdx.x * 16 + cl;
    int j  = blockIdx.y;
    float Acn = -expf(A_log[((size_t)layer * DI_ + c) * N_ST + n]);
    float Dpc = Dp[layer * DI_ + c];
    float carry = g_C0[j * GROUPS + c * N_ST + n];
    float p = 1.0f;
    int t0 = j * CLEN;
    if (j > 0) {
        for (int t = t0; t < t0 + CLEN; t++) {
            float dtv = g_dtl[(size_t)t * DI_ + c];
            float Cv  = __half2float(g_xdblh[(size_t)t * XDP + DTRANK + N_ST + n]);
            p *= __expf(dtv * Acn);
            float v = Cv * p * carry;
#pragma unroll
            for (int o = 8; o > 0; o >>= 1)
                v += __shfl_down_sync(0xffffffffu, v, o, 16);
            if (n == 0) {
                float xv = __half2float(g_xsh[(size_t)t * DI_ + c]);
                float z  = g_xz[(size_t)t * 2 * DI_ + DI_ + c];
                g_yh[(size_t)t * DI_ + c] = __float2half_rn(
                    (g_y[(size_t)t * DI_ + c] + v + xv * Dpc) * silu_f(z));
            }
        }
    } else {
        if (n == 0) {
            for (int t = t0; t < t0 + CLEN; t++) {
                float xv = __half2float(g_xsh[(size_t)t * DI_ + c]);
                float z  = g_xz[(size_t)t * 2 * DI_ + DI_ + c];
                g_yh[(size_t)t * DI_ + c] = __float2half_rn(
                    (g_y[(size_t)t * DI_ + c] + xv * Dpc) * silu_f(z));
            }
        }
    }
}

__global__ __launch_bounds__(256)
void ln_kernel(const float* __restrict__ gam, const float* __restrict__ bet, int layer) {
    int l = blockIdx.x;
    __shared__ float rsum[8], rsq[8];
    float sum = 0.0f, sq = 0.0f;
    for (int d = threadIdx.x; d < D_MODEL; d += 256) {
        float v = g_x[(size_t)l * D_MODEL + d] + g_tmp[(size_t)l * D_MODEL + d];
        sum += v; sq += v * v;
    }
#pragma unroll
    for (int o = 16; o > 0; o >>= 1) {
        sum += __shfl_down_sync(0xffffffffu, sum, o);
        sq  += __shfl_down_sync(0xffffffffu, sq, o);
    }
    int wid = threadIdx.x >> 5;
    if ((threadIdx.x & 31) == 0) { rsum[wid] = sum; rsq[wid] = sq; }
    __syncthreads();
    if (threadIdx.x == 0) {
        float s = 0.0f, q = 0.0f;
#pragma unroll
        for (int w = 0; w < 8; w++) { s += rsum[w]; q += rsq[w]; }
        rsum[0] = s; rsq[0] = q;
    }
    __syncthreads();
    float mu  = rsum[0] / (float)D_MODEL;
    float var = rsq[0] / (float)D_MODEL - mu * mu;
    float rinv = rsqrtf(var + 1e-5f);
    for (int d = threadIdx.x; d < D_MODEL; d += 256) {
        float v = g_x[(size_t)l * D_MODEL + d] + g_tmp[(size_t)l * D_MODEL + d];
        float o = (v - mu) * rinv * gam[layer * D_MODEL + d] + bet[layer * D_MODEL + d];
        g_x [(size_t)l * D_MODEL + d] = o;
        g_xh[(size_t)l * D_MODEL + d] = __float2half_rn(o);
    }
}

// ---------------- launch ----------------
extern "C" void kernel_launch(void* const* d_in, const int* in_sizes, int n_in,
                              void* d_out, int out_size) {
    const int*   tokens  = (const int*)  d_in[0];
    const float* emb     = (const float*)d_in[1];
    const float* in_w    = (const float*)d_in[2];
    const float* conv_w  = (const float*)d_in[3];
    const float* conv_b  = (const float*)d_in[4];
    const float* xproj_w = (const float*)d_in[5];
    const float* dt_w    = (const float*)d_in[6];
    const float* dt_b    = (const float*)d_in[7];
    const float* A_log   = (const float*)d_in[8];
    const float* Dp      = (const float*)d_in[9];
    const float* out_w   = (const float*)d_in[10];
    const float* ln_g    = (const float*)d_in[11];
    const float* ln_b    = (const float*)d_in[12];
    const float* head_w  = (const float*)d_in[13];
    float* out = (float*)d_out;

    static float *px = nullptr, *pxz, *pdtl, *py, *ptmp;
    static __half *pxh, *pxsh, *pxdblh, *pyh, *pwh;
    static __half *pwpad[NL_], *pdtw[NL_], *pwbig[NL_], *pwout[NL_];
    static cudaStream_t s1;
    static cudaEvent_t evFork, evWh, evJoin;
    static cudaEvent_t evIn[NL_], evPP[NL_], evOw[NL_];
    if (!px) {
        cudaGetSymbolAddress((void**)&pxz,    g_xz);
        cudaGetSymbolAddress((void**)&pdtl,   g_dtl);
        cudaGetSymbolAddress((void**)&py,     g_y);
        cudaGetSymbolAddress((void**)&ptmp,   g_tmp);
        cudaGetSymbolAddress((void**)&pxh,    g_xh);
        cudaGetSymbolAddress((void**)&pxsh,   g_xsh);
        cudaGetSymbolAddress((void**)&pxdblh, g_xdblh);
        cudaGetSymbolAddress((void**)&pyh,    g_yh);
        cudaGetSymbolAddress((void**)&pwh,    g_wh);
        __half* hb;
        cudaGetSymbolAddress((void**)&hb, g_wpad);
        for (int L = 0; L < NL_; L++) pwpad[L] = hb + (size_t)L * 256 * DI_;
        cudaGetSymbolAddress((void**)&hb, g_dtwpad);
        for (int L = 0; L < NL_; L++) pdtw[L] = hb + (size_t)L * DI_ * 64;
        cudaGetSymbolAddress((void**)&hb, g_wbig);
        for (int L = 0; L < NL_; L++) pwbig[L] = hb + (size_t)L * 2 * DI_ * D_MODEL;
        cudaGetSymbolAddress((void**)&hb, g_wout);
        for (int L = 0; L < NL_; L++) pwout[L] = hb + (size_t)L * D_MODEL * DI_;
        cudaFuncSetAttribute(gemm_h<false>,
                             cudaFuncAttributeMaxDynamicSharedMemorySize, SMEM_GEMM);
        cudaFuncSetAttribute(gemm_h<true>,
                             cudaFuncAttributeMaxDynamicSharedMemorySize, SMEM_GEMM);
        cudaStreamCreateWithFlags(&s1, cudaStreamNonBlocking);
        cudaEventCreateWithFlags(&evFork, cudaEventDisableTiming);
        cudaEventCreateWithFlags(&evWh,   cudaEventDisableTiming);
        cudaEventCreateWithFlags(&evJoin, cudaEventDisableTiming);
        for (int L = 0; L < NL_; L++) {
            cudaEventCreateWithFlags(&evIn[L], cudaEventDisableTiming);
            cudaEventCreateWithFlags(&evPP[L], cudaEventDisableTiming);
            cudaEventCreateWithFlags(&evOw[L], cudaEventDisableTiming);
        }
        cudaGetSymbolAddress((void**)&px, g_x);
    }

    cudaEventRecord(evFork, 0);
    cudaStreamWaitEvent(s1, evFork, 0);

    embed_kernel<<<(S_LEN * D_MODEL + 255) / 256, 256>>>(tokens, emb);          // idx 0

    roundcopy_h<<<(2 * DI_ * D_MODEL / 4 + 255) / 256, 256, 0, s1>>>(           // idx 1
        (__half2*)pwbig[0], (const float4*)in_w, 2 * DI_ * D_MODEL / 4);
    cudaEventRecord(evIn[0], s1);
    padw_kernel<<<(256 * DI_ + 255) / 256, 256, 0, s1>>>(xproj_w, 0);           // idx 2

    // in-proj L0 at launch idx 3 (profiled)
    cudaStreamWaitEvent(0, evIn[0], 0);
    gemm_h<false><<<dim3(S_LEN / 128, 2 * DI_ / 128), 256, SMEM_GEMM>>>(
        pxh, pwbig[0], pxz, D_MODEL, D_MODEL, D_MODEL, 2 * DI_);                // idx 3

    paddt_kernel<<<(DI_ * 64 + 255) / 256, 256, 0, s1>>>(dt_w, 0);
    cudaEventRecord(evPP[0], s1);
    roundcopy_h<<<(D_MODEL * DI_ / 4 + 255) / 256, 256, 0, s1>>>(
        (__half2*)pwout[0], (const float4*)out_w, D_MODEL * DI_ / 4);
    cudaEventRecord(evOw[0], s1);
    roundcopy_h<<<(2 * DI_ * D_MODEL / 4 + 255) / 256, 256, 0, s1>>>(
        (__half2*)pwbig[1], (const float4*)(in_w + (size_t)2 * DI_ * D_MODEL),
        2 * DI_ * D_MODEL / 4);
    cudaEventRecord(evIn[1], s1);
    padw_kernel<<<(256 * DI_ + 255) / 256, 256, 0, s1>>>(xproj_w, 1);
    paddt_kernel<<<(DI_ * 64 + 255) / 256, 256, 0, s1>>>(dt_w, 1);
    cudaEventRecord(evPP[1], s1);
    roundcopy_h<<<(D_MODEL * DI_ / 4 + 255) / 256, 256, 0, s1>>>(
        (__half2*)pwout[1], (const float4*)(out_w + (size_t)D_MODEL * DI_),
        D_MODEL * DI_ / 4);
    cudaEventRecord(evOw[1], s1);
    roundcopy_h<<<(VOCAB * D_MODEL / 4 + 255) / 256, 256, 0, s1>>>(
        (__half2*)pwh, (const float4*)head_w, VOCAB * D_MODEL / 4);
    cudaEventRecord(evWh, s1);
    cudaEventRecord(evJoin, s1);

    for (int L = 0; L < NL_; L++) {
        if (L > 0) {
            cudaStreamWaitEvent(0, evIn[L], 0);
            gemm_h<false><<<dim3(S_LEN / 128, 2 * DI_ / 128), 256, SMEM_GEMM>>>(
                pxh, pwbig[L], pxz, D_MODEL, D_MODEL, D_MODEL, 2 * DI_);
        }
        conv_silu_kernel<<<(S_LEN * DI_ + 255) / 256, 256>>>(conv_w, conv_b, L);

        cudaStreamWaitEvent(0, evPP[L], 0);
        // x-proj: [1024,1536]x[256,1536]^T -> half out
        gemm_h<true><<<dim3(S_LEN / 128, XDP / 128), 256, SMEM_GEMM>>>(
            pxsh, pwpad[L], pxdblh, DI_, DI_, DI_, XDP);
        // dt-proj: K=64
        gemm_h<false><<<dim3(S_LEN / 128, DI_ / 128), 256, SMEM_GEMM>>>(
            pxdblh, pdtw[L], pdtl, 64, XDP, 64, DI_);

        scan_p1<<<dim3(DI_ / 16, NCHUNK), 256>>>(A_log, dt_b, L);
        scan_p2<<<(GROUPS + 255) / 256, 256>>>();
        scan_p3<<<dim3(DI_ / 16, NCHUNK), 256>>>(A_log, Dp, L);

        cudaStreamWaitEvent(0, evOw[L], 0);
        gemm_h<false><<<dim3(S_LEN / 128, D_MODEL / 128), 256, SMEM_GEMM>>>(
            pyh, pwout[L], ptmp, DI_, DI_, DI_, D_MODEL);

        ln_kernel<<<S_LEN, 256>>>(ln_g, ln_b, L);
    }

    cudaStreamWaitEvent(0, evWh, 0);
    cudaStreamWaitEvent(0, evJoin, 0);
    gemm_h<false><<<dim3(S_LEN / 128, VOCAB / 128), 256, SMEM_GEMM>>>(
        pxh, pwh, out, D_MODEL, D_MODEL, D_MODEL, VOCAB);
}

// round 9
// speedup vs baseline: 1.3600x; 1.0738x over previous
#include <cuda_runtime.h>
#include <cuda_fp16.h>
#include <cstdint>
#include <math.h>

#define S_LEN   1024
#define D_MODEL 768
#define DI_     1536
#define N_ST    16
#define K_CONV  4
#define DTRANK  48
#define XDP     256
#define VOCAB   32000
#define NL_     2
#define NCHUNK  8
#define CLEN    128
#define GROUPS  (DI_ * N_ST)

// ---------------- scratch ----------------
__device__ __align__(128) float  g_x    [S_LEN * D_MODEL];
__device__ __align__(128) __half g_xh   [S_LEN * D_MODEL];
__device__ __align__(128) float  g_xz   [S_LEN * 2 * DI_];
__device__ __align__(128) __half g_xsh  [S_LEN * DI_];
__device__ __align__(128) __half g_xdblh[S_LEN * XDP];
__device__ __align__(128) float  g_dtl  [S_LEN * DI_];
__device__ __align__(128) float  g_y    [S_LEN * DI_];
__device__ __align__(128) __half g_yh   [S_LEN * DI_];
__device__ __align__(128) float  g_tmp  [S_LEN * D_MODEL];
__device__ __align__(128) __half g_wpad  [NL_][256 * DI_];
__device__ __align__(128) __half g_dtwpad[NL_][DI_ * 64];
__device__ __align__(128) __half g_wbig  [NL_][2 * DI_ * D_MODEL];
__device__ __align__(128) __half g_wout  [NL_][D_MODEL * DI_];
__device__ __align__(128) __half g_wh    [VOCAB * D_MODEL];
__device__ __align__(128) float  g_P  [NCHUNK * GROUPS];
__device__ __align__(128) float  g_H  [NCHUNK * GROUPS];
__device__ __align__(128) float  g_C0 [NCHUNK * GROUPS];

// ---------------- helpers ----------------
__device__ __forceinline__ uint32_t smem_u32(const void* p) {
    uint32_t a;
    asm("{ .reg .u64 t; cvta.to.shared.u64 t, %1; cvt.u32.u64 %0, t; }" : "=r"(a) : "l"(p));
    return a;
}
__device__ __forceinline__ float silu_f(float x) { return x / (1.0f + __expf(-x)); }

#define CP_ASYNC16(dst, src) \
    asm volatile("cp.async.cg.shared.global [%0], [%1], 16;" :: "r"(dst), "l"(src))
#define CP_COMMIT() asm volatile("cp.async.commit_group;" ::: "memory")
#define CP_WAIT(n)  asm volatile("cp.async.wait_group %0;" :: "n"(n) : "memory")
#define LDSM4(d0, d1, d2, d3, a) \
    asm volatile("ldmatrix.sync.aligned.m8n8.x4.shared.b16 {%0,%1,%2,%3}, [%4];" \
        : "=r"(d0), "=r"(d1), "=r"(d2), "=r"(d3) : "r"(a))

__device__ __forceinline__ void mma_f16(float* c, const uint32_t* a, const uint32_t* b) {
    asm volatile(
        "mma.sync.aligned.m16n8k16.row.col.f32.f16.f16.f32 "
        "{%0,%1,%2,%3}, {%4,%5,%6,%7}, {%8,%9}, {%0,%1,%2,%3};"
        : "+f"(c[0]), "+f"(c[1]), "+f"(c[2]), "+f"(c[3])
        : "r"(a[0]), "r"(a[1]), "r"(a[2]), "r"(a[3]), "r"(b[0]), "r"(b[1]));
}

// ---------------- fp16 GEMM big: 128x128, 8 warps (warp 64x32) ----------------
#define STG_B 16384
#define SMEM_GEMM (3 * 2 * STG_B)        // 98304

template<bool OH>
__global__ __launch_bounds__(256, 2)
void gemm_h(const __half* __restrict__ A, const __half* __restrict__ B,
            void* __restrict__ Cv, int K, int lda, int ldb, int ldc)
{
    extern __shared__ char smem[];
    const int tid = threadIdx.x, lane = tid & 31, wid = tid >> 5;
    const int wm = wid >> 2, wn = wid & 3;
    const int bm = blockIdx.x * 128, bn = blockIdx.y * 128;
    const int nc = K >> 6;
    const int lr = lane & 7, lg = lane >> 3;

    const uint32_t sb = smem_u32(smem);
    const __half* Ab = A + (size_t)bm * lda;
    const __half* Bb = B + (size_t)bn * ldb;

    auto loadA = [&](int chunk, int st) {
        uint32_t d0 = sb + st * (2 * STG_B);
        const __half* s0 = Ab + chunk * 64;
#pragma unroll
        for (int it = 0; it < 4; it++) {
            int i = tid + it * 256;
            int r = i >> 3, q = i & 7;
            uint32_t off = ((uint32_t)r << 7) | (((uint32_t)q << 4) ^ (((uint32_t)(r & 7)) << 4));
            CP_ASYNC16(d0 + off, s0 + (size_t)r * lda + q * 8);
        }
    };
    auto loadB = [&](int chunk, int st) {
        uint32_t d0 = sb + st * (2 * STG_B) + STG_B;
        const __half* s0 = Bb + chunk * 64;
#pragma unroll
        for (int it = 0; it < 4; it++) {
            int i = tid + it * 256;
            int r = i >> 3, q = i & 7;
            uint32_t off = ((uint32_t)r << 7) | (((uint32_t)q << 4) ^ (((uint32_t)(r & 7)) << 4));
            CP_ASYNC16(d0 + off, s0 + (size_t)r * ldb + q * 8);
        }
    };

    const int a_row0 = wm * 64 + ((lg & 1) << 3) + lr;
    const int a_coff = (lg >> 1) << 4;
    const int b_row0 = wn * 32 + ((lg & 2) << 2) + lr;
    const int b_coff = (lg & 1) << 4;
    const uint32_t sw = (uint32_t)lr << 4;

    float acc[4][4][4];
#pragma unroll
    for (int i = 0; i < 4; i++)
#pragma unroll
        for (int j = 0; j < 4; j++)
#pragma unroll
            for (int v = 0; v < 4; v++) acc[i][j][v] = 0.0f;

    int npre = nc < 2 ? nc : 2;
    for (int c = 0; c < npre; c++) { loadA(c, c); loadB(c, c); CP_COMMIT(); }

    for (int i = 0; i < nc; i++) {
        if (i + 2 < nc) { CP_WAIT(1); } else { CP_WAIT(0); }
        __syncthreads();
        if (i + 2 < nc) {
            int s2 = (i + 2) % 3;
            loadA(i + 2, s2); loadB(i + 2, s2); CP_COMMIT();
        }
        uint32_t abase = sb + (i % 3) * (2 * STG_B);
        uint32_t bbase = abase + STG_B;
#pragma unroll
        for (int ks = 0; ks < 4; ks++) {
            const uint32_t kb = (uint32_t)ks * 32;
            uint32_t afr[4][4];
#pragma unroll
            for (int mf = 0; mf < 4; mf++) {
                uint32_t ad = abase + (uint32_t)(a_row0 + mf * 16) * 128 + ((kb + a_coff) ^ sw);
                LDSM4(afr[mf][0], afr[mf][1], afr[mf][2], afr[mf][3], ad);
            }
            uint32_t bfr[4][2];
#pragma unroll
            for (int p = 0; p < 2; p++) {
                uint32_t bd = bbase + (uint32_t)(b_row0 + p * 16) * 128 + ((kb + b_coff) ^ sw);
                LDSM4(bfr[2 * p][0], bfr[2 * p][1], bfr[2 * p + 1][0], bfr[2 * p + 1][1], bd);
            }
#pragma unroll
            for (int mf = 0; mf < 4; mf++)
#pragma unroll
                for (int nf = 0; nf < 4; nf++)
                    mma_f16(acc[mf][nf], afr[mf], bfr[nf]);
        }
    }

#pragma unroll
    for (int mf = 0; mf < 4; mf++) {
        int row = bm + wm * 64 + mf * 16 + (lane >> 2);
#pragma unroll
        for (int nf = 0; nf < 4; nf++) {
            int col = bn + wn * 32 + nf * 8 + 2 * (lane & 3);
            if (OH) {
                __half* C = (__half*)Cv;
                *(__half2*)(C + (size_t)row * ldc + col) =
                    __floats2half2_rn(acc[mf][nf][0], acc[mf][nf][1]);
                *(__half2*)(C + (size_t)(row + 8) * ldc + col) =
                    __floats2half2_rn(acc[mf][nf][2], acc[mf][nf][3]);
            } else {
                float* C = (float*)Cv;
                *(float2*)(C + (size_t)row * ldc + col) =
                    make_float2(acc[mf][nf][0], acc[mf][nf][1]);
                *(float2*)(C + (size_t)(row + 8) * ldc + col) =
                    make_float2(acc[mf][nf][2], acc[mf][nf][3]);
            }
        }
    }
}

// ---------------- fp16 GEMM small: 64x64, 4 warps (warp 32x32) -----------------
#define STG_S 8192
#define SMEM_GS (3 * 2 * STG_S)          // 49152

template<bool OH>
__global__ __launch_bounds__(128, 4)
void gemm_s(const __half* __restrict__ A, const __half* __restrict__ B,
            void* __restrict__ Cv, int K, int lda, int ldb, int ldc)
{
    extern __shared__ char smem[];
    const int tid = threadIdx.x, lane = tid & 31, wid = tid >> 5;
    const int wm = wid >> 1, wn = wid & 1;
    const int bm = blockIdx.x * 64, bn = blockIdx.y * 64;
    const int nc = K >> 6;
    const int lr = lane & 7, lg = lane >> 3;

    const uint32_t sb = smem_u32(smem);
    const __half* Ab = A + (size_t)bm * lda;
    const __half* Bb = B + (size_t)bn * ldb;

    auto loadA = [&](int chunk, int st) {
        uint32_t d0 = sb + st * (2 * STG_S);
        const __half* s0 = Ab + chunk * 64;
#pragma unroll
        for (int it = 0; it < 4; it++) {
            int i = tid + it * 128;
            int r = i >> 3, q = i & 7;
            uint32_t off = ((uint32_t)r << 7) | (((uint32_t)q << 4) ^ (((uint32_t)(r & 7)) << 4));
            CP_ASYNC16(d0 + off, s0 + (size_t)r * lda + q * 8);
        }
    };
    auto loadB = [&](int chunk, int st) {
        uint32_t d0 = sb + st * (2 * STG_S) + STG_S;
        const __half* s0 = Bb + chunk * 64;
#pragma unroll
        for (int it = 0; it < 4; it++) {
            int i = tid + it * 128;
            int r = i >> 3, q = i & 7;
            uint32_t off = ((uint32_t)r << 7) | (((uint32_t)q << 4) ^ (((uint32_t)(r & 7)) << 4));
            CP_ASYNC16(d0 + off, s0 + (size_t)r * ldb + q * 8);
        }
    };

    const int a_row0 = wm * 32 + ((lg & 1) << 3) + lr;
    const int a_coff = (lg >> 1) << 4;
    const int b_row0 = wn * 32 + ((lg & 2) << 2) + lr;
    const int b_coff = (lg & 1) << 4;
    const uint32_t sw = (uint32_t)lr << 4;

    float acc[2][4][4];
#pragma unroll
    for (int i = 0; i < 2; i++)
#pragma unroll
        for (int j = 0; j < 4; j++)
#pragma unroll
            for (int v = 0; v < 4; v++) acc[i][j][v] = 0.0f;

    int npre = nc < 2 ? nc : 2;
    for (int c = 0; c < npre; c++) { loadA(c, c); loadB(c, c); CP_COMMIT(); }

    for (int i = 0; i < nc; i++) {
        if (i + 2 < nc) { CP_WAIT(1); } else { CP_WAIT(0); }
        __syncthreads();
        if (i + 2 < nc) {
            int s2 = (i + 2) % 3;
            loadA(i + 2, s2); loadB(i + 2, s2); CP_COMMIT();
        }
        uint32_t abase = sb + (i % 3) * (2 * STG_S);
        uint32_t bbase = abase + STG_S;
#pragma unroll
        for (int ks = 0; ks < 4; ks++) {
            const uint32_t kb = (uint32_t)ks * 32;
            uint32_t afr[2][4];
#pragma unroll
            for (int mf = 0; mf < 2; mf++) {
                uint32_t ad = abase + (uint32_t)(a_row0 + mf * 16) * 128 + ((kb + a_coff) ^ sw);
                LDSM4(afr[mf][0], afr[mf][1], afr[mf][2], afr[mf][3], ad);
            }
            uint32_t bfr[4][2];
#pragma unroll
            for (int p = 0; p < 2; p++) {
                uint32_t bd = bbase + (uint32_t)(b_row0 + p * 16) * 128 + ((kb + b_coff) ^ sw);
                LDSM4(bfr[2 * p][0], bfr[2 * p][1], bfr[2 * p + 1][0], bfr[2 * p + 1][1], bd);
            }
#pragma unroll
            for (int mf = 0; mf < 2; mf++)
#pragma unroll
                for (int nf = 0; nf < 4; nf++)
                    mma_f16(acc[mf][nf], afr[mf], bfr[nf]);
        }
    }

#pragma unroll
    for (int mf = 0; mf < 2; mf++) {
        int row = bm + wm * 32 + mf * 16 + (lane >> 2);
#pragma unroll
        for (int nf = 0; nf < 4; nf++) {
            int col = bn + wn * 32 + nf * 8 + 2 * (lane & 3);
            if (OH) {
                __half* C = (__half*)Cv;
                *(__half2*)(C + (size_t)row * ldc + col) =
                    __floats2half2_rn(acc[mf][nf][0], acc[mf][nf][1]);
                *(__half2*)(C + (size_t)(row + 8) * ldc + col) =
                    __floats2half2_rn(acc[mf][nf][2], acc[mf][nf][3]);
            } else {
                float* C = (float*)Cv;
                *(float2*)(C + (size_t)row * ldc + col) =
                    make_float2(acc[mf][nf][0], acc[mf][nf][1]);
                *(float2*)(C + (size_t)(row + 8) * ldc + col) =
                    make_float2(acc[mf][nf][2], acc[mf][nf][3]);
            }
        }
    }
}

// ---------------- elementwise / small kernels ----------------
__global__ void roundcopy_h(__half2* __restrict__ dst, const float4* __restrict__ src, int n4) {
    int i = blockIdx.x * blockDim.x + threadIdx.x;
    if (i < n4) {
        float4 v = src[i];
        dst[2 * i]     = __floats2half2_rn(v.x, v.y);
        dst[2 * i + 1] = __floats2half2_rn(v.z, v.w);
    }
}

__global__ void embed_kernel(const int* __restrict__ tokens,
                             const float* __restrict__ emb) {
    int i = blockIdx.x * blockDim.x + threadIdx.x;
    if (i < S_LEN * D_MODEL) {
        int l = i / D_MODEL, d = i - l * D_MODEL;
        float e = emb[(size_t)tokens[l] * D_MODEL + d];
        g_x[i]  = e;
        g_xh[i] = __float2half_rn(e);
    }
}

__global__ void padw_kernel(const float* __restrict__ xw, int L) {
    int i = blockIdx.x * 256 + threadIdx.x;
    if (i >= 256 * DI_) return;
    int row = i / DI_, col = i - row * DI_;
    g_wpad[L][i] = (row < 80) ? __float2half_rn(xw[((size_t)L * 80 + row) * DI_ + col])
                              : __half(0.0f);
}

__global__ void paddt_kernel(const float* __restrict__ dw, int L) {
    int i = blockIdx.x * 256 + threadIdx.x;
    if (i >= DI_ * 64) return;
    int row = i >> 6, col = i & 63;
    g_dtwpad[L][i] = (col < DTRANK) ? __float2half_rn(dw[((size_t)L * DI_ + row) * DTRANK + col])
                                    : __half(0.0f);
}

__global__ void conv_silu_kernel(const float* __restrict__ conv_w,
                                 const float* __restrict__ conv_b, int layer) {
    int i = blockIdx.x * blockDim.x + threadIdx.x;
    if (i >= S_LEN * DI_) return;
    int t = i / DI_, c = i - t * DI_;
    const float* w = conv_w + ((size_t)layer * DI_ + c) * K_CONV;
    float acc = conv_b[layer * DI_ + c];
#pragma unroll
    for (int k = 0; k < K_CONV; k++) {
        int tt = t - (K_CONV - 1) + k;
        if (tt >= 0) acc += w[k] * g_xz[(size_t)tt * 2 * DI_ + c];
    }
    g_xsh[i] = __float2half_rn(silu_f(acc));
}

// ---------------- chunked selective scan ----------------
__global__ __launch_bounds__(256)
void scan_p1(const float* __restrict__ A_log, const float* __restrict__ dt_b, int layer) {
    int n  = threadIdx.x & 15;
    int cl = threadIdx.x >> 4;
    int c  = blockIdx.x * 16 + cl;
    int j  = blockIdx.y;
    float Acn  = -expf(A_log[((size_t)layer * DI_ + c) * N_ST + n]);
    float bias = dt_b[layer * DI_ + c];
    float h = 0.0f, p = 1.0f;
    int t0 = j * CLEN;
    for (int t = t0; t < t0 + CLEN; t++) {
        float a   = g_dtl[(size_t)t * DI_ + c] + bias;
        float dtv = (a > 20.0f) ? a : log1pf(__expf(a));
        float xv  = __half2float(g_xsh[(size_t)t * DI_ + c]);
        float Bv  = __half2float(g_xdblh[(size_t)t * XDP + DTRANK + n]);
        float Cv  = __half2float(g_xdblh[(size_t)t * XDP + DTRANK + N_ST + n]);
        float dA  = __expf(dtv * Acn);
        h = dA * h + dtv * Bv * xv;
        p *= dA;
        float v = h * Cv;
#pragma unroll
        for (int o = 8; o > 0; o >>= 1)
            v += __shfl_down_sync(0xffffffffu, v, o, 16);
        if (n == 0) {
            g_y[(size_t)t * DI_ + c] = v;
            g_dtl[(size_t)t * DI_ + c] = dtv;
        }
    }
    int idx = c * N_ST + n;
    g_P[j * GROUPS + idx] = p;
    g_H[j * GROUPS + idx] = h;
}

__global__ void scan_p2() {
    int idx = blockIdx.x * blockDim.x + threadIdx.x;
    if (idx >= GROUPS) return;
    float carry = 0.0f;
#pragma unroll
    for (int j = 0; j < NCHUNK; j++) {
        g_C0[j * GROUPS + idx] = carry;
        carry = g_H[j * GROUPS + idx] + g_P[j * GROUPS + idx] * carry;
    }
}

__global__ __launch_bounds__(256)
void scan_p3(const float* __restrict__ A_log, const float* __restrict__ Dp, int layer) {
    int n  = threadIdx.x & 15;
    int cl = threadIdx.x >> 4;
    int c  = blockIdx.x * 16 + cl;
    int j  = blockIdx.y;
    float Acn = -expf(A_log[((size_t)layer * DI_ + c) * N_ST + n]);
    float Dpc = Dp[layer * DI_ + c];
    float carry = g_C0[j * GROUPS + c * N_ST + n];
    float p = 1.0f;
    int t0 = j * CLEN;
    if (j > 0) {
        for (int t = t0; t < t0 + CLEN; t++) {
            float dtv = g_dtl[(size_t)t * DI_ + c];
            float Cv  = __half2float(g_xdblh[(size_t)t * XDP + DTRANK + N_ST + n]);
            p *= __expf(dtv * Acn);
            float v = Cv * p * carry;
#pragma unroll
            for (int o = 8; o > 0; o >>= 1)
                v += __shfl_down_sync(0xffffffffu, v, o, 16);
            if (n == 0) {
                float xv = __half2float(g_xsh[(size_t)t * DI_ + c]);
                float z  = g_xz[(size_t)t * 2 * DI_ + DI_ + c];
                g_yh[(size_t)t * DI_ + c] = __float2half_rn(
                    (g_y[(size_t)t * DI_ + c] + v + xv * Dpc) * silu_f(z));
            }
        }
    } else {
        if (n == 0) {
            for (int t = t0; t < t0 + CLEN; t++) {
                float xv = __half2float(g_xsh[(size_t)t * DI_ + c]);
                float z  = g_xz[(size_t)t * 2 * DI_ + DI_ + c];
                g_yh[(size_t)t * DI_ + c] = __float2half_rn(
                    (g_y[(size_t)t * DI_ + c] + xv * Dpc) * silu_f(z));
            }
        }
    }
}

__global__ __launch_bounds__(256)
void ln_kernel(const float* __restrict__ gam, const float* __restrict__ bet, int layer) {
    int l = blockIdx.x;
    __shared__ float rsum[8], rsq[8];
    float sum = 0.0f, sq = 0.0f;
    for (int d = threadIdx.x; d < D_MODEL; d += 256) {
        float v = g_x[(size_t)l * D_MODEL + d] + g_tmp[(size_t)l * D_MODEL + d];
        sum += v; sq += v * v;
    }
#pragma unroll
    for (int o = 16; o > 0; o >>= 1) {
        sum += __shfl_down_sync(0xffffffffu, sum, o);
        sq  += __shfl_down_sync(0xffffffffu, sq, o);
    }
    int wid = threadIdx.x >> 5;
    if ((threadIdx.x & 31) == 0) { rsum[wid] = sum; rsq[wid] = sq; }
    __syncthreads();
    if (threadIdx.x == 0) {
        float s = 0.0f, q = 0.0f;
#pragma unroll
        for (int w = 0; w < 8; w++) { s += rsum[w]; q += rsq[w]; }
        rsum[0] = s; rsq[0] = q;
    }
    __syncthreads();
    float mu  = rsum[0] / (float)D_MODEL;
    float var = rsq[0] / (float)D_MODEL - mu * mu;
    float rinv = rsqrtf(var + 1e-5f);
    for (int d = threadIdx.x; d < D_MODEL; d += 256) {
        float v = g_x[(size_t)l * D_MODEL + d] + g_tmp[(size_t)l * D_MODEL + d];
        float o = (v - mu) * rinv * gam[layer * D_MODEL + d] + bet[layer * D_MODEL + d];
        g_x [(size_t)l * D_MODEL + d] = o;
        g_xh[(size_t)l * D_MODEL + d] = __float2half_rn(o);
    }
}

// ---------------- launch ----------------
extern "C" void kernel_launch(void* const* d_in, const int* in_sizes, int n_in,
                              void* d_out, int out_size) {
    const int*   tokens  = (const int*)  d_in[0];
    const float* emb     = (const float*)d_in[1];
    const float* in_w    = (const float*)d_in[2];
    const float* conv_w  = (const float*)d_in[3];
    const float* conv_b  = (const float*)d_in[4];
    const float* xproj_w = (const float*)d_in[5];
    const float* dt_w    = (const float*)d_in[6];
    const float* dt_b    = (const float*)d_in[7];
    const float* A_log   = (const float*)d_in[8];
    const float* Dp      = (const float*)d_in[9];
    const float* out_w   = (const float*)d_in[10];
    const float* ln_g    = (const float*)d_in[11];
    const float* ln_b    = (const float*)d_in[12];
    const float* head_w  = (const float*)d_in[13];
    float* out = (float*)d_out;

    static float *px = nullptr, *pxz, *pdtl, *py, *ptmp;
    static __half *pxh, *pxsh, *pxdblh, *pyh, *pwh;
    static __half *pwpad[NL_], *pdtw[NL_], *pwbig[NL_], *pwout[NL_];
    static cudaStream_t s1;
    static cudaEvent_t evFork, evWh, evJoin;
    static cudaEvent_t evIn[NL_], evPP[NL_], evOw[NL_];
    if (!px) {
        cudaGetSymbolAddress((void**)&pxz,    g_xz);
        cudaGetSymbolAddress((void**)&pdtl,   g_dtl);
        cudaGetSymbolAddress((void**)&py,     g_y);
        cudaGetSymbolAddress((void**)&ptmp,   g_tmp);
        cudaGetSymbolAddress((void**)&pxh,    g_xh);
        cudaGetSymbolAddress((void**)&pxsh,   g_xsh);
        cudaGetSymbolAddress((void**)&pxdblh, g_xdblh);
        cudaGetSymbolAddress((void**)&pyh,    g_yh);
        cudaGetSymbolAddress((void**)&pwh,    g_wh);
        __half* hb;
        cudaGetSymbolAddress((void**)&hb, g_wpad);
        for (int L = 0; L < NL_; L++) pwpad[L] = hb + (size_t)L * 256 * DI_;
        cudaGetSymbolAddress((void**)&hb, g_dtwpad);
        for (int L = 0; L < NL_; L++) pdtw[L] = hb + (size_t)L * DI_ * 64;
        cudaGetSymbolAddress((void**)&hb, g_wbig);
        for (int L = 0; L < NL_; L++) pwbig[L] = hb + (size_t)L * 2 * DI_ * D_MODEL;
        cudaGetSymbolAddress((void**)&hb, g_wout);
        for (int L = 0; L < NL_; L++) pwout[L] = hb + (size_t)L * D_MODEL * DI_;
        cudaFuncSetAttribute(gemm_h<false>,
                             cudaFuncAttributeMaxDynamicSharedMemorySize, SMEM_GEMM);
        cudaFuncSetAttribute(gemm_h<true>,
                             cudaFuncAttributeMaxDynamicSharedMemorySize, SMEM_GEMM);
        cudaFuncSetAttribute(gemm_s<false>,
                             cudaFuncAttributeMaxDynamicSharedMemorySize, SMEM_GS);
        cudaFuncSetAttribute(gemm_s<true>,
                             cudaFuncAttributeMaxDynamicSharedMemorySize, SMEM_GS);
        cudaStreamCreateWithFlags(&s1, cudaStreamNonBlocking);
        cudaEventCreateWithFlags(&evFork, cudaEventDisableTiming);
        cudaEventCreateWithFlags(&evWh,   cudaEventDisableTiming);
        cudaEventCreateWithFlags(&evJoin, cudaEventDisableTiming);
        for (int L = 0; L < NL_; L++) {
            cudaEventCreateWithFlags(&evIn[L], cudaEventDisableTiming);
            cudaEventCreateWithFlags(&evPP[L], cudaEventDisableTiming);
            cudaEventCreateWithFlags(&evOw[L], cudaEventDisableTiming);
        }
        cudaGetSymbolAddress((void**)&px, g_x);
    }

    cudaEventRecord(evFork, 0);
    cudaStreamWaitEvent(s1, evFork, 0);

    embed_kernel<<<(S_LEN * D_MODEL + 255) / 256, 256>>>(tokens, emb);          // idx 0

    roundcopy_h<<<(2 * DI_ * D_MODEL / 4 + 255) / 256, 256, 0, s1>>>(           // idx 1
        (__half2*)pwbig[0], (const float4*)in_w, 2 * DI_ * D_MODEL / 4);
    cudaEventRecord(evIn[0], s1);
    padw_kernel<<<(256 * DI_ + 255) / 256, 256, 0, s1>>>(xproj_w, 0);           // idx 2

    // in-proj L0 (profiled launch idx 3): small-tile variant
    cudaStreamWaitEvent(0, evIn[0], 0);
    gemm_s<false><<<dim3(S_LEN / 64, 2 * DI_ / 64), 128, SMEM_GS>>>(
        pxh, pwbig[0], pxz, D_MODEL, D_MODEL, D_MODEL, 2 * DI_);                // idx 3

    paddt_kernel<<<(DI_ * 64 + 255) / 256, 256, 0, s1>>>(dt_w, 0);
    cudaEventRecord(evPP[0], s1);
    roundcopy_h<<<(D_MODEL * DI_ / 4 + 255) / 256, 256, 0, s1>>>(
        (__half2*)pwout[0], (const float4*)out_w, D_MODEL * DI_ / 4);
    cudaEventRecord(evOw[0], s1);
    roundcopy_h<<<(2 * DI_ * D_MODEL / 4 + 255) / 256, 256, 0, s1>>>(
        (__half2*)pwbig[1], (const float4*)(in_w + (size_t)2 * DI_ * D_MODEL),
        2 * DI_ * D_MODEL / 4);
    cudaEventRecord(evIn[1], s1);
    padw_kernel<<<(256 * DI_ + 255) / 256, 256, 0, s1>>>(xproj_w, 1);
    paddt_kernel<<<(DI_ * 64 + 255) / 256, 256, 0, s1>>>(dt_w, 1);
    cudaEventRecord(evPP[1], s1);
    roundcopy_h<<<(D_MODEL * DI_ / 4 + 255) / 256, 256, 0, s1>>>(
        (__half2*)pwout[1], (const float4*)(out_w + (size_t)D_MODEL * DI_),
        D_MODEL * DI_ / 4);
    cudaEventRecord(evOw[1], s1);
    roundcopy_h<<<(VOCAB * D_MODEL / 4 + 255) / 256, 256, 0, s1>>>(
        (__half2*)pwh, (const float4*)head_w, VOCAB * D_MODEL / 4);
    cudaEventRecord(evWh, s1);
    cudaEventRecord(evJoin, s1);

    for (int L = 0; L < NL_; L++) {
        if (L > 0) {
            cudaStreamWaitEvent(0, evIn[L], 0);
            gemm_s<false><<<dim3(S_LEN / 64, 2 * DI_ / 64), 128, SMEM_GS>>>(
                pxh, pwbig[L], pxz, D_MODEL, D_MODEL, D_MODEL, 2 * DI_);
        }
        conv_silu_kernel<<<(S_LEN * DI_ + 255) / 256, 256>>>(conv_w, conv_b, L);

        cudaStreamWaitEvent(0, evPP[L], 0);
        gemm_s<true><<<dim3(S_LEN / 64, XDP / 64), 128, SMEM_GS>>>(
            pxsh, pwpad[L], pxdblh, DI_, DI_, DI_, XDP);
        gemm_s<false><<<dim3(S_LEN / 64, DI_ / 64), 128, SMEM_GS>>>(
            pxdblh, pdtw[L], pdtl, 64, XDP, 64, DI_);

        scan_p1<<<dim3(DI_ / 16, NCHUNK), 256>>>(A_log, dt_b, L);
        scan_p2<<<(GROUPS + 255) / 256, 256>>>();
        scan_p3<<<dim3(DI_ / 16, NCHUNK), 256>>>(A_log, Dp, L);

        cudaStreamWaitEvent(0, evOw[L], 0);
        gemm_s<false><<<dim3(S_LEN / 64, D_MODEL / 64), 128, SMEM_GS>>>(
            pyh, pwout[L], ptmp, DI_, DI_, DI_, D_MODEL);

        ln_kernel<<<S_LEN, 256>>>(ln_g, ln_b, L);
    }

    cudaStreamWaitEvent(0, evWh, 0);
    cudaStreamWaitEvent(0, evJoin, 0);
    gemm_h<false><<<dim3(S_LEN / 128, VOCAB / 128), 256, SMEM_GEMM>>>(
        pxh, pwh, out, D_MODEL, D_MODEL, D_MODEL, VOCAB);
}

// round 10
// speedup vs baseline: 2.1668x; 1.5933x over previous
#include <cuda_runtime.h>
#include <cuda_fp16.h>
#include <cstdint>
#include <math.h>

#define S_LEN   1024
#define D_MODEL 768
#define DI_     1536
#define N_ST    16
#define K_CONV  4
#define DTRANK  48
#define XDP     256
#define VOCAB   32000
#define NL_     2
#define NCHUNK  32
#define CLEN    32
#define GROUPS  (DI_ * N_ST)

// ---------------- scratch ----------------
__device__ __align__(128) float  g_x    [S_LEN * D_MODEL];
__device__ __align__(128) __half g_xh   [S_LEN * D_MODEL];
__device__ __align__(128) float  g_xz   [S_LEN * 2 * DI_];
__device__ __align__(128) __half g_xsh  [S_LEN * DI_];
__device__ __align__(128) __half g_xdblh[S_LEN * XDP];
__device__ __align__(128) float  g_dtl  [S_LEN * DI_];     // softplus(dt) after dt-GEMM
__device__ __align__(128) float  g_y    [S_LEN * DI_];
__device__ __align__(128) __half g_yh   [S_LEN * DI_];
__device__ __align__(128) float  g_tmp  [S_LEN * D_MODEL];
__device__ __align__(128) __half g_wpad  [NL_][256 * DI_];
__device__ __align__(128) __half g_dtwpad[NL_][DI_ * 64];
__device__ __align__(128) __half g_wbig  [NL_][2 * DI_ * D_MODEL];
__device__ __align__(128) __half g_wout  [NL_][D_MODEL * DI_];
__device__ __align__(128) __half g_wh    [VOCAB * D_MODEL];
__device__ __align__(128) float  g_P  [NCHUNK * GROUPS];
__device__ __align__(128) float  g_H  [NCHUNK * GROUPS];
__device__ __align__(128) float  g_C0 [NCHUNK * GROUPS];

// ---------------- helpers ----------------
__device__ __forceinline__ uint32_t smem_u32(const void* p) {
    uint32_t a;
    asm("{ .reg .u64 t; cvta.to.shared.u64 t, %1; cvt.u32.u64 %0, t; }" : "=r"(a) : "l"(p));
    return a;
}
__device__ __forceinline__ float silu_f(float x) { return x / (1.0f + __expf(-x)); }
__device__ __forceinline__ float sp_f(float a)   { return (a > 20.0f) ? a : log1pf(__expf(a)); }

#define CP_ASYNC16(dst, src) \
    asm volatile("cp.async.cg.shared.global [%0], [%1], 16;" :: "r"(dst), "l"(src))
#define CP_COMMIT() asm volatile("cp.async.commit_group;" ::: "memory")
#define CP_WAIT(n)  asm volatile("cp.async.wait_group %0;" :: "n"(n) : "memory")
#define LDSM4(d0, d1, d2, d3, a) \
    asm volatile("ldmatrix.sync.aligned.m8n8.x4.shared.b16 {%0,%1,%2,%3}, [%4];" \
        : "=r"(d0), "=r"(d1), "=r"(d2), "=r"(d3) : "r"(a))

__device__ __forceinline__ void mma_f16(float* c, const uint32_t* a, const uint32_t* b) {
    asm volatile(
        "mma.sync.aligned.m16n8k16.row.col.f32.f16.f16.f32 "
        "{%0,%1,%2,%3}, {%4,%5,%6,%7}, {%8,%9}, {%0,%1,%2,%3};"
        : "+f"(c[0]), "+f"(c[1]), "+f"(c[2]), "+f"(c[3])
        : "r"(a[0]), "r"(a[1]), "r"(a[2]), "r"(a[3]), "r"(b[0]), "r"(b[1]));
}

// ---------------- fp16 GEMM: 64x64, 4 warps, 3-stage, 4 CTAs/SM ---------------
// OM: 0 = fp32 out, 1 = half out, 2 = fp32 softplus(acc + bias[col]) out
#define STG_S 8192
#define SMEM_GS (3 * 2 * STG_S)          // 49152

template<int OM>
__global__ __launch_bounds__(128, 4)
void gemm_s(const __half* __restrict__ A, const __half* __restrict__ B,
            void* __restrict__ Cv, int K, int lda, int ldb, int ldc,
            const float* __restrict__ bias)
{
    extern __shared__ char smem[];
    const int tid = threadIdx.x, lane = tid & 31, wid = tid >> 5;
    const int wm = wid >> 1, wn = wid & 1;
    const int bm = blockIdx.x * 64, bn = blockIdx.y * 64;
    const int nc = K >> 6;
    const int lr = lane & 7, lg = lane >> 3;

    const uint32_t sb = smem_u32(smem);
    const __half* Ab = A + (size_t)bm * lda;
    const __half* Bb = B + (size_t)bn * ldb;

    auto loadA = [&](int chunk, int st) {
        uint32_t d0 = sb + st * (2 * STG_S);
        const __half* s0 = Ab + chunk * 64;
#pragma unroll
        for (int it = 0; it < 4; it++) {
            int i = tid + it * 128;
            int r = i >> 3, q = i & 7;
            uint32_t off = ((uint32_t)r << 7) | (((uint32_t)q << 4) ^ (((uint32_t)(r & 7)) << 4));
            CP_ASYNC16(d0 + off, s0 + (size_t)r * lda + q * 8);
        }
    };
    auto loadB = [&](int chunk, int st) {
        uint32_t d0 = sb + st * (2 * STG_S) + STG_S;
        const __half* s0 = Bb + chunk * 64;
#pragma unroll
        for (int it = 0; it < 4; it++) {
            int i = tid + it * 128;
            int r = i >> 3, q = i & 7;
            uint32_t off = ((uint32_t)r << 7) | (((uint32_t)q << 4) ^ (((uint32_t)(r & 7)) << 4));
            CP_ASYNC16(d0 + off, s0 + (size_t)r * ldb + q * 8);
        }
    };

    const int a_row0 = wm * 32 + ((lg & 1) << 3) + lr;
    const int a_coff = (lg >> 1) << 4;
    const int b_row0 = wn * 32 + ((lg & 2) << 2) + lr;
    const int b_coff = (lg & 1) << 4;
    const uint32_t sw = (uint32_t)lr << 4;

    float acc[2][4][4];
#pragma unroll
    for (int i = 0; i < 2; i++)
#pragma unroll
        for (int j = 0; j < 4; j++)
#pragma unroll
            for (int v = 0; v < 4; v++) acc[i][j][v] = 0.0f;

    int npre = nc < 2 ? nc : 2;
    for (int c = 0; c < npre; c++) { loadA(c, c); loadB(c, c); CP_COMMIT(); }

    for (int i = 0; i < nc; i++) {
        if (i + 2 < nc) { CP_WAIT(1); } else { CP_WAIT(0); }
        __syncthreads();
        if (i + 2 < nc) {
            int s2 = (i + 2) % 3;
            loadA(i + 2, s2); loadB(i + 2, s2); CP_COMMIT();
        }
        uint32_t abase = sb + (i % 3) * (2 * STG_S);
        uint32_t bbase = abase + STG_S;
#pragma unroll
        for (int ks = 0; ks < 4; ks++) {
            const uint32_t kb = (uint32_t)ks * 32;
            uint32_t afr[2][4];
#pragma unroll
            for (int mf = 0; mf < 2; mf++) {
                uint32_t ad = abase + (uint32_t)(a_row0 + mf * 16) * 128 + ((kb + a_coff) ^ sw);
                LDSM4(afr[mf][0], afr[mf][1], afr[mf][2], afr[mf][3], ad);
            }
            uint32_t bfr[4][2];
#pragma unroll
            for (int p = 0; p < 2; p++) {
                uint32_t bd = bbase + (uint32_t)(b_row0 + p * 16) * 128 + ((kb + b_coff) ^ sw);
                LDSM4(bfr[2 * p][0], bfr[2 * p][1], bfr[2 * p + 1][0], bfr[2 * p + 1][1], bd);
            }
#pragma unroll
            for (int mf = 0; mf < 2; mf++)
#pragma unroll
                for (int nf = 0; nf < 4; nf++)
                    mma_f16(acc[mf][nf], afr[mf], bfr[nf]);
        }
    }

#pragma unroll
    for (int mf = 0; mf < 2; mf++) {
        int row = bm + wm * 32 + mf * 16 + (lane >> 2);
#pragma unroll
        for (int nf = 0; nf < 4; nf++) {
            int col = bn + wn * 32 + nf * 8 + 2 * (lane & 3);
            if (OM == 1) {
                __half* C = (__half*)Cv;
                *(__half2*)(C + (size_t)row * ldc + col) =
                    __floats2half2_rn(acc[mf][nf][0], acc[mf][nf][1]);
                *(__half2*)(C + (size_t)(row + 8) * ldc + col) =
                    __floats2half2_rn(acc[mf][nf][2], acc[mf][nf][3]);
            } else if (OM == 2) {
                float* C = (float*)Cv;
                float b0 = bias[col], b1 = bias[col + 1];
                *(float2*)(C + (size_t)row * ldc + col) =
                    make_float2(sp_f(acc[mf][nf][0] + b0), sp_f(acc[mf][nf][1] + b1));
                *(float2*)(C + (size_t)(row + 8) * ldc + col) =
                    make_float2(sp_f(acc[mf][nf][2] + b0), sp_f(acc[mf][nf][3] + b1));
            } else {
                float* C = (float*)Cv;
                *(float2*)(C + (size_t)row * ldc + col) =
                    make_float2(acc[mf][nf][0], acc[mf][nf][1]);
                *(float2*)(C + (size_t)(row + 8) * ldc + col) =
                    make_float2(acc[mf][nf][2], acc[mf][nf][3]);
            }
        }
    }
}

// ---------------- elementwise / small kernels ----------------
__global__ void roundcopy_h(__half2* __restrict__ dst, const float4* __restrict__ src, int n4) {
    int i = blockIdx.x * blockDim.x + threadIdx.x;
    if (i < n4) {
        float4 v = src[i];
        dst[2 * i]     = __floats2half2_rn(v.x, v.y);
        dst[2 * i + 1] = __floats2half2_rn(v.z, v.w);
    }
}

__global__ void embed_kernel(const int* __restrict__ tokens,
                             const float* __restrict__ emb) {
    int i = blockIdx.x * blockDim.x + threadIdx.x;
    if (i < S_LEN * D_MODEL) {
        int l = i / D_MODEL, d = i - l * D_MODEL;
        float e = emb[(size_t)tokens[l] * D_MODEL + d];
        g_x[i]  = e;
        g_xh[i] = __float2half_rn(e);
    }
}

__global__ void padw_kernel(const float* __restrict__ xw, int L) {
    int i = blockIdx.x * 256 + threadIdx.x;
    if (i >= 256 * DI_) return;
    int row = i / DI_, col = i - row * DI_;
    g_wpad[L][i] = (row < 80) ? __float2half_rn(xw[((size_t)L * 80 + row) * DI_ + col])
                              : __half(0.0f);
}

__global__ void paddt_kernel(const float* __restrict__ dw, int L) {
    int i = blockIdx.x * 256 + threadIdx.x;
    if (i >= DI_ * 64) return;
    int row = i >> 6, col = i & 63;
    g_dtwpad[L][i] = (col < DTRANK) ? __float2half_rn(dw[((size_t)L * DI_ + row) * DTRANK + col])
                                    : __half(0.0f);
}

__global__ void conv_silu_kernel(const float* __restrict__ conv_w,
                                 const float* __restrict__ conv_b, int layer) {
    int i = blockIdx.x * blockDim.x + threadIdx.x;
    if (i >= S_LEN * DI_) return;
    int t = i / DI_, c = i - t * DI_;
    const float* w = conv_w + ((size_t)layer * DI_ + c) * K_CONV;
    float acc = conv_b[layer * DI_ + c];
#pragma unroll
    for (int k = 0; k < K_CONV; k++) {
        int tt = t - (K_CONV - 1) + k;
        if (tt >= 0) acc += w[k] * g_xz[(size_t)tt * 2 * DI_ + c];
    }
    g_xsh[i] = __float2half_rn(silu_f(acc));
}

// ---------------- chunked scan, per-channel layout ----------------
// p1: thread = (channel, chunk). h[16] in regs; B/C warp-uniform broadcast.
__global__ __launch_bounds__(128)
void scan_p1(const float* __restrict__ A_log, int layer) {
    int c = blockIdx.x * 128 + threadIdx.x;
    int j = blockIdx.y;
    float Acn[N_ST];
#pragma unroll
    for (int n = 0; n < N_ST; n++)
        Acn[n] = -expf(A_log[((size_t)layer * DI_ + c) * N_ST + n]);
    float h[N_ST];
#pragma unroll
    for (int n = 0; n < N_ST; n++) h[n] = 0.0f;
    float Sdt = 0.0f;
    int t0 = j * CLEN;
    for (int t = t0; t < t0 + CLEN; t++) {
        float dtv = g_dtl[(size_t)t * DI_ + c];
        float xv  = __half2float(g_xsh[(size_t)t * DI_ + c]);
        float dx  = dtv * xv;
        Sdt += dtv;
        const __half2* bc = (const __half2*)(g_xdblh + (size_t)t * XDP + DTRANK);
        float y = 0.0f;
#pragma unroll
        for (int q = 0; q < 8; q++) {
            float2 B2 = __half22float2(bc[q]);
            float2 C2 = __half22float2(bc[8 + q]);
            float dA0 = __expf(dtv * Acn[2 * q]);
            float dA1 = __expf(dtv * Acn[2 * q + 1]);
            h[2 * q]     = dA0 * h[2 * q]     + dx * B2.x;
            h[2 * q + 1] = dA1 * h[2 * q + 1] + dx * B2.y;
            y += h[2 * q] * C2.x + h[2 * q + 1] * C2.y;
        }
        g_y[(size_t)t * DI_ + c] = y;
    }
    float* Hp = g_H + (size_t)j * GROUPS + (size_t)c * N_ST;
    float* Pp = g_P + (size_t)j * GROUPS + (size_t)c * N_ST;
#pragma unroll
    for (int n = 0; n < N_ST; n++) {
        Hp[n] = h[n];
        Pp[n] = __expf(Sdt * Acn[n]);
    }
}

__global__ void scan_p2() {
    int idx = blockIdx.x * blockDim.x + threadIdx.x;
    if (idx >= GROUPS) return;
    float carry = 0.0f;
#pragma unroll
    for (int j = 0; j < NCHUNK; j++) {
        g_C0[j * GROUPS + idx] = carry;
        carry = g_H[j * GROUPS + idx] + g_P[j * GROUPS + idx] * carry;
    }
}

// p3: carry correction + fused gate, per-channel layout.
__global__ __launch_bounds__(128)
void scan_p3(const float* __restrict__ A_log, const float* __restrict__ Dp, int layer) {
    int c = blockIdx.x * 128 + threadIdx.x;
    int j = blockIdx.y;
    float Dpc = Dp[layer * DI_ + c];
    int t0 = j * CLEN;
    if (j == 0) {
        for (int t = t0; t < t0 + CLEN; t++) {
            float xv = __half2float(g_xsh[(size_t)t * DI_ + c]);
            float z  = g_xz[(size_t)t * 2 * DI_ + DI_ + c];
            g_yh[(size_t)t * DI_ + c] = __float2half_rn(
                (g_y[(size_t)t * DI_ + c] + xv * Dpc) * silu_f(z));
        }
        return;
    }
    float Acn[N_ST], w[N_ST];
    const float* Cp = g_C0 + (size_t)j * GROUPS + (size_t)c * N_ST;
#pragma unroll
    for (int n = 0; n < N_ST; n++) {
        Acn[n] = -expf(A_log[((size_t)layer * DI_ + c) * N_ST + n]);
        w[n]   = Cp[n];
    }
    float S = 0.0f;
    for (int t = t0; t < t0 + CLEN; t++) {
        float dtv = g_dtl[(size_t)t * DI_ + c];
        S += dtv;
        const __half2* cc = (const __half2*)(g_xdblh + (size_t)t * XDP + DTRANK + N_ST);
        float v = 0.0f;
#pragma unroll
        for (int q = 0; q < 8; q++) {
            float2 C2 = __half22float2(cc[q]);
            v += C2.x * __expf(S * Acn[2 * q])     * w[2 * q];
            v += C2.y * __expf(S * Acn[2 * q + 1]) * w[2 * q + 1];
        }
        float xv = __half2float(g_xsh[(size_t)t * DI_ + c]);
        float z  = g_xz[(size_t)t * 2 * DI_ + DI_ + c];
        g_yh[(size_t)t * DI_ + c] = __float2half_rn(
            (g_y[(size_t)t * DI_ + c] + v + xv * Dpc) * silu_f(z));
    }
}

__global__ __launch_bounds__(256)
void ln_kernel(const float* __restrict__ gam, const float* __restrict__ bet, int layer) {
    int l = blockIdx.x;
    __shared__ float rsum[8], rsq[8];
    float sum = 0.0f, sq = 0.0f;
    for (int d = threadIdx.x; d < D_MODEL; d += 256) {
        float v = g_x[(size_t)l * D_MODEL + d] + g_tmp[(size_t)l * D_MODEL + d];
        sum += v; sq += v * v;
    }
#pragma unroll
    for (int o = 16; o > 0; o >>= 1) {
        sum += __shfl_down_sync(0xffffffffu, sum, o);
        sq  += __shfl_down_sync(0xffffffffu, sq, o);
    }
    int wid = threadIdx.x >> 5;
    if ((threadIdx.x & 31) == 0) { rsum[wid] = sum; rsq[wid] = sq; }
    __syncthreads();
    if (threadIdx.x == 0) {
        float s = 0.0f, q = 0.0f;
#pragma unroll
        for (int w = 0; w < 8; w++) { s += rsum[w]; q += rsq[w]; }
        rsum[0] = s; rsq[0] = q;
    }
    __syncthreads();
    float mu  = rsum[0] / (float)D_MODEL;
    float var = rsq[0] / (float)D_MODEL - mu * mu;
    float rinv = rsqrtf(var + 1e-5f);
    for (int d = threadIdx.x; d < D_MODEL; d += 256) {
        float v = g_x[(size_t)l * D_MODEL + d] + g_tmp[(size_t)l * D_MODEL + d];
        float o = (v - mu) * rinv * gam[layer * D_MODEL + d] + bet[layer * D_MODEL + d];
        g_x [(size_t)l * D_MODEL + d] = o;
        g_xh[(size_t)l * D_MODEL + d] = __float2half_rn(o);
    }
}

// ---------------- launch ----------------
extern "C" void kernel_launch(void* const* d_in, const int* in_sizes, int n_in,
                              void* d_out, int out_size) {
    const int*   tokens  = (const int*)  d_in[0];
    const float* emb     = (const float*)d_in[1];
    const float* in_w    = (const float*)d_in[2];
    const float* conv_w  = (const float*)d_in[3];
    const float* conv_b  = (const float*)d_in[4];
    const float* xproj_w = (const float*)d_in[5];
    const float* dt_w    = (const float*)d_in[6];
    const float* dt_b    = (const float*)d_in[7];
    const float* A_log   = (const float*)d_in[8];
    const float* Dp      = (const float*)d_in[9];
    const float* out_w   = (const float*)d_in[10];
    const float* ln_g    = (const float*)d_in[11];
    const float* ln_b    = (const float*)d_in[12];
    const float* head_w  = (const float*)d_in[13];
    float* out = (float*)d_out;

    static float *px = nullptr, *pxz, *pdtl, *py, *ptmp;
    static __half *pxh, *pxsh, *pxdblh, *pyh, *pwh;
    static __half *pwpad[NL_], *pdtw[NL_], *pwbig[NL_], *pwout[NL_];
    static cudaStream_t s1;
    static cudaEvent_t evFork, evWh, evJoin;
    static cudaEvent_t evIn[NL_], evPP[NL_], evOw[NL_];
    if (!px) {
        cudaGetSymbolAddress((void**)&pxz,    g_xz);
        cudaGetSymbolAddress((void**)&pdtl,   g_dtl);
        cudaGetSymbolAddress((void**)&py,     g_y);
        cudaGetSymbolAddress((void**)&ptmp,   g_tmp);
        cudaGetSymbolAddress((void**)&pxh,    g_xh);
        cudaGetSymbolAddress((void**)&pxsh,   g_xsh);
        cudaGetSymbolAddress((void**)&pxdblh, g_xdblh);
        cudaGetSymbolAddress((void**)&pyh,    g_yh);
        cudaGetSymbolAddress((void**)&pwh,    g_wh);
        __half* hb;
        cudaGetSymbolAddress((void**)&hb, g_wpad);
        for (int L = 0; L < NL_; L++) pwpad[L] = hb + (size_t)L * 256 * DI_;
        cudaGetSymbolAddress((void**)&hb, g_dtwpad);
        for (int L = 0; L < NL_; L++) pdtw[L] = hb + (size_t)L * DI_ * 64;
        cudaGetSymbolAddress((void**)&hb, g_wbig);
        for (int L = 0; L < NL_; L++) pwbig[L] = hb + (size_t)L * 2 * DI_ * D_MODEL;
        cudaGetSymbolAddress((void**)&hb, g_wout);
        for (int L = 0; L < NL_; L++) pwout[L] = hb + (size_t)L * D_MODEL * DI_;
        cudaFuncSetAttribute(gemm_s<0>,
                             cudaFuncAttributeMaxDynamicSharedMemorySize, SMEM_GS);
        cudaFuncSetAttribute(gemm_s<1>,
                             cudaFuncAttributeMaxDynamicSharedMemorySize, SMEM_GS);
        cudaFuncSetAttribute(gemm_s<2>,
                             cudaFuncAttributeMaxDynamicSharedMemorySize, SMEM_GS);
        cudaStreamCreateWithFlags(&s1, cudaStreamNonBlocking);
        cudaEventCreateWithFlags(&evFork, cudaEventDisableTiming);
        cudaEventCreateWithFlags(&evWh,   cudaEventDisableTiming);
        cudaEventCreateWithFlags(&evJoin, cudaEventDisableTiming);
        for (int L = 0; L < NL_; L++) {
            cudaEventCreateWithFlags(&evIn[L], cudaEventDisableTiming);
            cudaEventCreateWithFlags(&evPP[L], cudaEventDisableTiming);
            cudaEventCreateWithFlags(&evOw[L], cudaEventDisableTiming);
        }
        cudaGetSymbolAddress((void**)&px, g_x);
    }

    cudaEventRecord(evFork, 0);
    cudaStreamWaitEvent(s1, evFork, 0);

    embed_kernel<<<(S_LEN * D_MODEL + 255) / 256, 256>>>(tokens, emb);          // idx 0

    roundcopy_h<<<(2 * DI_ * D_MODEL / 4 + 255) / 256, 256, 0, s1>>>(           // idx 1
        (__half2*)pwbig[0], (const float4*)in_w, 2 * DI_ * D_MODEL / 4);
    cudaEventRecord(evIn[0], s1);
    padw_kernel<<<(256 * DI_ + 255) / 256, 256, 0, s1>>>(xproj_w, 0);           // idx 2

    // in-proj L0 (profiled launch idx 3)
    cudaStreamWaitEvent(0, evIn[0], 0);
    gemm_s<0><<<dim3(S_LEN / 64, 2 * DI_ / 64), 128, SMEM_GS>>>(
        pxh, pwbig[0], pxz, D_MODEL, D_MODEL, D_MODEL, 2 * DI_, nullptr);       // idx 3

    paddt_kernel<<<(DI_ * 64 + 255) / 256, 256, 0, s1>>>(dt_w, 0);
    cudaEventRecord(evPP[0], s1);
    roundcopy_h<<<(D_MODEL * DI_ / 4 + 255) / 256, 256, 0, s1>>>(
        (__half2*)pwout[0], (const float4*)out_w, D_MODEL * DI_ / 4);
    cudaEventRecord(evOw[0], s1);
    roundcopy_h<<<(2 * DI_ * D_MODEL / 4 + 255) / 256, 256, 0, s1>>>(
        (__half2*)pwbig[1], (const float4*)(in_w + (size_t)2 * DI_ * D_MODEL),
        2 * DI_ * D_MODEL / 4);
    cudaEventRecord(evIn[1], s1);
    padw_kernel<<<(256 * DI_ + 255) / 256, 256, 0, s1>>>(xproj_w, 1);
    paddt_kernel<<<(DI_ * 64 + 255) / 256, 256, 0, s1>>>(dt_w, 1);
    cudaEventRecord(evPP[1], s1);
    roundcopy_h<<<(D_MODEL * DI_ / 4 + 255) / 256, 256, 0, s1>>>(
        (__half2*)pwout[1], (const float4*)(out_w + (size_t)D_MODEL * DI_),
        D_MODEL * DI_ / 4);
    cudaEventRecord(evOw[1], s1);
    roundcopy_h<<<(VOCAB * D_MODEL / 4 + 255) / 256, 256, 0, s1>>>(
        (__half2*)pwh, (const float4*)head_w, VOCAB * D_MODEL / 4);
    cudaEventRecord(evWh, s1);
    cudaEventRecord(evJoin, s1);

    for (int L = 0; L < NL_; L++) {
        if (L > 0) {
            cudaStreamWaitEvent(0, evIn[L], 0);
            gemm_s<0><<<dim3(S_LEN / 64, 2 * DI_ / 64), 128, SMEM_GS>>>(
                pxh, pwbig[L], pxz, D_MODEL, D_MODEL, D_MODEL, 2 * DI_, nullptr);
        }
        conv_silu_kernel<<<(S_LEN * DI_ + 255) / 256, 256>>>(conv_w, conv_b, L);

        cudaStreamWaitEvent(0, evPP[L], 0);
        gemm_s<1><<<dim3(S_LEN / 64, XDP / 64), 128, SMEM_GS>>>(
            pxsh, pwpad[L], pxdblh, DI_, DI_, DI_, XDP, nullptr);
        // dt-proj with fused bias + softplus epilogue
        gemm_s<2><<<dim3(S_LEN / 64, DI_ / 64), 128, SMEM_GS>>>(
            pxdblh, pdtw[L], pdtl, 64, XDP, 64, DI_, dt_b + (size_t)L * DI_);

        scan_p1<<<dim3(DI_ / 128, NCHUNK), 128>>>(A_log, L);
        scan_p2<<<(GROUPS + 255) / 256, 256>>>();
        scan_p3<<<dim3(DI_ / 128, NCHUNK), 128>>>(A_log, Dp, L);

        cudaStreamWaitEvent(0, evOw[L], 0);
        gemm_s<0><<<dim3(S_LEN / 64, D_MODEL / 64), 128, SMEM_GS>>>(
            pyh, pwout[L], ptmp, DI_, DI_, DI_, D_MODEL, nullptr);

        ln_kernel<<<S_LEN, 256>>>(ln_g, ln_b, L);
    }

    cudaStreamWaitEvent(0, evWh, 0);
    cudaStreamWaitEvent(0, evJoin, 0);
    gemm_s<0><<<dim3(S_LEN / 64, VOCAB / 64), 128, SMEM_GS>>>(
        pxh, pwh, out, D_MODEL, D_MODEL, D_MODEL, VOCAB, nullptr);
}